// round 13
// baseline (speedup 1.0000x reference)
#include <cuda_runtime.h>

#define EPSV 1e-5f
#define B_   16
#define T_   2048
#define S_   2112        // padded stride for global conv buffers

// Global buffers:
__device__ __align__(128) float g_r1 [B_*64*S_];
__device__ __align__(128) float g_r2p[B_*S_*32];
__device__ __align__(128) float g_r3p[B_*S_*16];
__device__ __align__(128) float g_feats[B_*T_*16];
__device__ __align__(128) float g_h1  [B_*T_*64];    // h1 stream (producer -> mid)
__device__ __align__(128) float g_pre1[B_*T_*256];   // layer1 input projection (mid -> consumer)
__device__ int g_done[B_*8];                         // bnd chunk arrival counters (64 each)
__device__ int g_flag0[B_];
__device__ int g_flag1[B_];

// ======================= Phase A: merged global conv stack =======================
// XP[i] = x[i-49] for 49<=i<=2096 else 0.
// One CTA per (u-block of 64, batch): conv1 halo in smem -> conv2(+4 halo) -> conv3.
#define CA_SMEM_FLOATS 25216

__global__ void __launch_bounds__(256, 2) convA_kernel(
    const float* __restrict__ x,
    const float* __restrict__ c1w, const float* __restrict__ c1b,
    const float* __restrict__ g1, const float* __restrict__ b1p,
    const float* __restrict__ m1, const float* __restrict__ v1,
    const float* __restrict__ c2w, const float* __restrict__ c2b,
    const float* __restrict__ g2, const float* __restrict__ b2p,
    const float* __restrict__ m2, const float* __restrict__ v2,
    const float* __restrict__ c3w, const float* __restrict__ c3b,
    const float* __restrict__ g3, const float* __restrict__ b3p,
    const float* __restrict__ m3, const float* __restrict__ v3)
{
    extern __shared__ float sm[];
    float* w1s = sm;               // 576
    float* w2s = sm + 576;         // 14336  [(c1*7+k)*32 + c2]
    float* w3s = sm + 14912;       // 2560   [(c2*5+k)*16 + c3]
    float* s1  = sm + 17472; float* e1 = sm + 17536;
    float* s2  = sm + 17600; float* e2 = sm + 17632;
    float* s3  = sm + 17664; float* e3 = sm + 17680;
    float* xw  = sm + 17696;       // 84
    float* r1t = sm + 17792;       // 64*80
    float* r2t = sm + 22912;       // 32*72

    const int tid = threadIdx.x;
    const int b = blockIdx.y;
    const int u0 = blockIdx.x * 64;

    if (blockIdx.x == 0 && b == 0) {             // reset pipeline flags each replay
        if (tid < B_*8) g_done[tid] = 0;
        else if (tid < B_*8 + B_) g_flag0[tid - B_*8] = 0;
        else if (tid < B_*8 + 2*B_) g_flag1[tid - B_*8 - B_] = 0;
    }

    for (int i = tid; i < 576; i += 256) w1s[i] = c1w[i];
    for (int i = tid; i < 14336; i += 256) {
        int c2 = i / 448; int r = i % 448; int c1 = r / 7; int k = r % 7;
        w2s[(c1*7 + k)*32 + c2] = c2w[i];
    }
    for (int i = tid; i < 2560; i += 256) {
        int c3 = i / 160; int r = i % 160; int cc = r / 5; int k = r % 5;
        w3s[(cc*5 + k)*16 + c3] = c3w[i];
    }
    if (tid < 64) {
        float s = g1[tid] * rsqrtf(v1[tid] + EPSV);
        s1[tid] = s; e1[tid] = (c1b[tid] - m1[tid]) * s + b1p[tid];
    } else if (tid < 96) {
        int c = tid - 64;
        float s = g2[c] * rsqrtf(v2[c] + EPSV);
        s2[c] = s; e2[c] = (c2b[c] - m2[c]) * s + b2p[c];
    } else if (tid < 112) {
        int c = tid - 96;
        float s = g3[c] * rsqrtf(v3[c] + EPSV);
        s3[c] = s; e3[c] = (c3b[c] - m3[c]) * s + b3p[c];
    } else if (tid >= 128 && tid < 211) {
        int j = tid - 128;                        // xw[j] = XP[u0-9+j], j<83
        int i = u0 - 9 + j;
        xw[j] = (i >= 49 && i <= 2096) ? x[b*2048 + i - 49] : 0.f;
    }
    __syncthreads();

    // ---- conv1: 64 ch x 74 positions (halo for conv2+conv3) ----
    for (int idx = tid; idx < 64*74; idx += 256) {
        int c = idx / 74, i = idx - (idx / 74) * 74;
        float acc = 0.f;
        #pragma unroll
        for (int k = 0; k < 9; ++k) acc += w1s[c*9 + k] * xw[i + k];
        float r = acc * s1[c] + e1[c];
        r = r > 0.f ? r : 0.f;
        r1t[c*80 + i] = r;
        int u = u0 + i;
        if (i < 64 && u <= 2106) g_r1[(b*64 + c)*S_ + u] = r;
    }
    __syncthreads();

    // ---- conv2: 32 ch x 68 positions (4-pos halo for conv3) ----
    {
        const int c2 = tid & 31, slot = tid >> 5;   // 8 slots x 9 positions
        float acc[9];
        #pragma unroll
        for (int j = 0; j < 9; ++j) acc[j] = 0.f;
        for (int c1 = 0; c1 < 64; ++c1) {
            const float* rp = r1t + c1*80 + slot*9;
            float v[15];
            #pragma unroll
            for (int i = 0; i < 15; ++i) v[i] = rp[i];
            const float* wp = w2s + c1*224 + c2;
            #pragma unroll
            for (int k = 0; k < 7; ++k) {
                float wv = wp[k*32];
                #pragma unroll
                for (int j = 0; j < 9; ++j) acc[j] += wv * v[k + j];
            }
        }
        float ss = s2[c2], bb = e2[c2];
        #pragma unroll
        for (int j = 0; j < 9; ++j) {
            int i = slot*9 + j;
            if (i < 68) {
                float pre = acc[j] * ss + bb;
                r2t[c2*72 + i] = pre > 0.f ? pre : 0.f;
                int u = u0 + i;
                if (i < 64 && u <= 2100)
                    g_r2p[((size_t)b*S_ + u)*32 + c2] = pre;   // PRE-act, chan-last
            }
        }
    }
    __syncthreads();

    // ---- conv3: 16 ch x 64 positions ----
    {
        const int c3 = tid & 15, slot = tid >> 4;   // 16 slots x 4 positions
        float acc[4] = {0.f, 0.f, 0.f, 0.f};
        for (int cc = 0; cc < 32; ++cc) {
            const float* rp = r2t + cc*72 + slot*4;
            float v[8];
            #pragma unroll
            for (int i = 0; i < 8; ++i) v[i] = rp[i];
            const float* wp = w3s + cc*80 + c3;
            #pragma unroll
            for (int k = 0; k < 5; ++k) {
                float wv = wp[k*16];
                #pragma unroll
                for (int j = 0; j < 4; ++j) acc[j] += wv * v[k + j];
            }
        }
        float ss = s3[c3], bb = e3[c3];
        #pragma unroll
        for (int j = 0; j < 4; ++j) {
            int u = u0 + slot*4 + j;
            if (u <= 2096)
                g_r3p[((size_t)b*S_ + u)*16 + c3] = acc[j] * ss + bb;   // PRE-act, chan-last
        }
    }
}

// ======================= Fused Phase B + LSTM + FC (single launch) =====
// grid 1072: blocks 0..15 producers, 16..31 mid, 32..47 consumers(+FC), 48..1071 bnd.
// bnd CTAs never wait; lstm CTAs at low indices -> wave-1 resident. Deadlock-free.
#define BND_SMEM_FLOATS (14336 + 2560 + 576 + 176 + 64 + 4096 + 3072 + 256)
#define NBND  1024
#define NGRP  8

__device__ __forceinline__ float sigf(float x)  { return __fdividef(1.f, 1.f + __expf(-x)); }
__device__ __forceinline__ float tanhq(float x) { return __fdividef(2.f, 1.f + __expf(-2.f*x)) - 1.f; }

__device__ __forceinline__ unsigned long long pk2(float a, float b) {
    unsigned long long r;
    asm("mov.b64 %0, {%1, %2};" : "=l"(r) : "f"(a), "f"(b));
    return r;
}
__device__ __forceinline__ void fma2(unsigned long long& d,
                                     unsigned long long a, unsigned long long b) {
    asm("fma.rn.f32x2 %0, %1, %2, %0;" : "+l"(d) : "l"(a), "l"(b));
}
__device__ __forceinline__ float2 upk2(unsigned long long v) {
    float2 f;
    asm("mov.b64 {%0, %1}, %2;" : "=f"(f.x), "=f"(f.y) : "l"(v));
    return f;
}
__device__ __forceinline__ void relstore(int* p, int v) {
    asm volatile("st.release.gpu.global.s32 [%0], %1;" :: "l"(p), "r"(v) : "memory");
}
__device__ __forceinline__ int acqload(const int* p) {
    int v;
    asm volatile("ld.acquire.gpu.global.s32 %0, [%1];" : "=r"(v) : "l"(p) : "memory");
    return v;
}
__device__ __forceinline__ float gact(int g, float v) {
    return ((g >> 6) == 2) ? tanhq(v) : sigf(v);   // gate order: i, f, g(tanh), o
}

__global__ void __launch_bounds__(256, 2) bnd_lstm_kernel(
    const float* __restrict__ x,
    const float* __restrict__ c1w, const float* __restrict__ c1b,
    const float* __restrict__ g1, const float* __restrict__ b1p,
    const float* __restrict__ m1, const float* __restrict__ v1,
    const float* __restrict__ c2w,
    const float* __restrict__ g2, const float* __restrict__ v2,
    const float* __restrict__ c3w,
    const float* __restrict__ g3, const float* __restrict__ v3,
    const float* __restrict__ wih0, const float* __restrict__ whh0,
    const float* __restrict__ bih0, const float* __restrict__ bhh0,
    const float* __restrict__ wih1, const float* __restrict__ whh1,
    const float* __restrict__ bih1, const float* __restrict__ bhh1,
    const float* __restrict__ fc1w, const float* __restrict__ fc1b,
    const float* __restrict__ fc2w, const float* __restrict__ fc2b,
    float* __restrict__ out)
{
    extern __shared__ float sm[];
    const int tid = threadIdx.x;

    if (blockIdx.x >= 48) {
        // ==================== bnd: boundary corrections -> feats ====================
        float* w2s    = sm;               // 14336
        float* w3s    = sm + 14336;       // 2560
        float* w1s    = sm + 16896;       // 576
        float* s1s    = sm + 17472;       // 64
        float* e1s    = sm + 17536;       // 64
        float* s2s    = sm + 17600;       // 32
        float* s3s    = sm + 17632;       // 16 (+pad to 17648)
        float* xs     = sm + 17648;       // 64
        float* dstage = sm + 17712;       // 4096
        float* stage3 = sm + 21808;       // 3072
        float* fbuf   = sm + 24880;       // 256

        const int bid = blockIdx.x - 48;
        const int b  = bid >> 6;          // batch
        const int jj = bid & 63;          // CTA slot within batch

        for (int i = tid; i < 14336; i += 256) {
            int c2 = i / 448; int r = i % 448; int c1 = r / 7; int k = r % 7;
            w2s[(c1*7 + k)*32 + c2] = c2w[i];
        }
        for (int i = tid; i < 2560; i += 256) {
            int c3 = i / 160; int r = i % 160; int cc = r / 5; int k = r % 5;
            w3s[(cc*5 + k)*16 + c3] = c3w[i];
        }
        for (int i = tid; i < 576; i += 256) w1s[i] = c1w[i];
        if (tid < 64) {
            float s = g1[tid] * rsqrtf(v1[tid] + EPSV);
            s1s[tid] = s; e1s[tid] = (c1b[tid] - m1[tid]) * s + b1p[tid];
        } else if (tid < 96) {
            int c = tid - 64;
            s2s[c] = g2[c] * rsqrtf(v2[c] + EPSV);
        } else if (tid < 112) {
            int c = tid - 96;
            s3s[c] = g3[c] * rsqrtf(v3[c] + EPSV);
        }
        __syncthreads();

        for (int it = 0; it < NGRP; ++it) {
            const int t0 = ((it << 6) + jj) * 4;

            // ---- 1) stage x values ----
            if (tid < 64) {
                int w = tid >> 4, r = tid & 15;
                int side = r >> 3, j = r & 7;
                int i = t0 + w + (side ? 42 + j : j);
                float v = (i >= 49 && i <= 2096) ? x[b*2048 + i - 49] : 0.f;
                xs[side*32 + w*8 + j] = v;
            }
            __syncthreads();

            // ---- 2) stage delta1 ----
            for (int s = tid; s < 4096; s += 256) {
                int qi = s & 7, c1 = (s >> 3) & 63, side = (s >> 9) & 1, w = s >> 10;
                int t = t0 + w;
                float val = 0.f;
                if (qi < 7) {
                    if (side == 0) {
                        float gl = g_r1[(b*64 + c1)*S_ + t + qi + 2];
                        if (qi < 3) val = -gl;
                        else {
                            int q = qi - 3;
                            float pre = 0.f;
                            #pragma unroll
                            for (int k = 0; k < 9; ++k)
                                if (k >= 4 - q) pre += w1s[c1*9 + k] * xs[w*8 + q - 4 + k];
                            float rv = pre * s1s[c1] + e1s[c1];
                            val = (rv > 0.f ? rv : 0.f) - gl;
                        }
                    } else {
                        float gl = g_r1[(b*64 + c1)*S_ + t + 51 + qi];
                        if (qi >= 4) val = -gl;
                        else {
                            int q = 46 + qi;
                            float pre = 0.f;
                            #pragma unroll
                            for (int k = 0; k < 9; ++k)
                                if (k <= 53 - q) pre += w1s[c1*9 + k] * xs[32 + w*8 + qi + k];
                            float rv = pre * s1s[c1] + e1s[c1];
                            val = (rv > 0.f ? rv : 0.f) - gl;
                        }
                    }
                }
                dstage[s] = val;
            }
            __syncthreads();

            // ---- 3) conv2 correction -> stage3 ----
            {
                const int c2 = tid & 31, side = (tid >> 5) & 1, w = tid >> 6;
                const int t = t0 + w;
                float acc[7];
                #pragma unroll
                for (int p = 0; p < 7; ++p) acc[p] = 0.f;

                for (int c1 = 0; c1 < 64; ++c1) {
                    const float* dp = dstage + ((w*2 + side)*64 + c1)*8;
                    float4 A = *(const float4*)dp;
                    float4 Bv = *(const float4*)(dp + 4);
                    float d[8] = {A.x, A.y, A.z, A.w, Bv.x, Bv.y, Bv.z, Bv.w};
                    const float* wp = w2s + c1*224 + c2;
                    float wk[7];
                    #pragma unroll
                    for (int k = 0; k < 7; ++k) wk[k] = wp[k*32];
                    if (side == 0) {
                        #pragma unroll
                        for (int p = 0; p < 7; ++p)
                            #pragma unroll
                            for (int k = 0; k < 7; ++k)
                                if (k + p <= 6) acc[p] += wk[k] * d[p + k];
                    } else {
                        #pragma unroll
                        for (int p = 0; p < 7; ++p)
                            #pragma unroll
                            for (int k = 0; k < 7; ++k)
                                if (k >= 6 - p) acc[p] += wk[k] * d[p + k - 6];
                    }
                }

                const float s2v = s2s[c2];
                float* sp = stage3 + ((w*2 + side)*32 + c2)*12;
                const float* gpb = g_r2p + ((size_t)b*S_ + t)*32 + c2;
                if (side == 0) {
                    #pragma unroll
                    for (int p = 0; p < 7; ++p) {
                        float gpre = gpb[(p + 2)*32];
                        float pre = gpre + s2v * acc[p];
                        sp[2 + p] = (pre > 0.f ? pre : 0.f) - (gpre > 0.f ? gpre : 0.f);
                    }
                    float e0 = gpb[0], e1v = gpb[32];
                    sp[0] = -(e0 > 0.f ? e0 : 0.f);
                    sp[1] = -(e1v > 0.f ? e1v : 0.f);
                } else {
                    #pragma unroll
                    for (int p = 0; p < 7; ++p) {
                        float gpre = gpb[(45 + p)*32];
                        float pre = gpre + s2v * acc[p];
                        sp[p] = (pre > 0.f ? pre : 0.f) - (gpre > 0.f ? gpre : 0.f);
                    }
                    float e0 = gpb[52*32], e1v = gpb[53*32];
                    sp[7] = -(e0 > 0.f ? e0 : 0.f);
                    sp[8] = -(e1v > 0.f ? e1v : 0.f);
                }
                sp[9] = 0.f; sp[10] = 0.f; sp[11] = 0.f;
            }
            __syncthreads();

            // ---- 4) conv3 correction + interior sums ----
            if (tid < 128) {
                const int c3 = tid & 15, ws = tid >> 4;
                const int side = ws & 1, w = ws >> 1;
                const int t = t0 + w;
                float acc[9];
                #pragma unroll
                for (int p = 0; p < 9; ++p) acc[p] = 0.f;

                for (int c2 = 0; c2 < 32; ++c2) {
                    const float* dp = stage3 + (ws*32 + c2)*12;
                    float4 A = *(const float4*)dp;
                    float4 Bv = *(const float4*)(dp + 4);
                    float C = dp[8];
                    float d[9] = {A.x, A.y, A.z, A.w, Bv.x, Bv.y, Bv.z, Bv.w, C};
                    const float* wp = w3s + c2*80 + c3;
                    float wk[5];
                    #pragma unroll
                    for (int k = 0; k < 5; ++k) wk[k] = wp[k*16];
                    if (side == 0) {
                        #pragma unroll
                        for (int p = 0; p < 9; ++p)
                            #pragma unroll
                            for (int k = 0; k < 5; ++k)
                                if (p + k <= 8) acc[p] += wk[k] * d[p + k];
                    } else {
                        #pragma unroll
                        for (int p = 0; p < 9; ++p)
                            #pragma unroll
                            for (int k = 0; k < 5; ++k)
                                if (k >= 4 - p) acc[p] += wk[k] * d[p + k - 4];
                    }
                }

                float sum = 0.f;
                const float s3v = s3s[c3];
                const float* rp = g_r3p + ((size_t)b*S_ + t)*16 + c3;
                #pragma unroll
                for (int j = 0; j < 9; ++j) {
                    int P = side ? 41 + j : j;
                    float pre = rp[P*16] + s3v * acc[j];
                    sum += pre > 0.f ? pre : 0.f;
                }
                fbuf[ws*16 + c3] = sum;
            } else {
                const int tt = tid - 128;
                const int c3 = tt & 15, ws = tt >> 4;
                const int side = ws & 1, w = ws >> 1;
                const int t = t0 + w;
                const float* rp = g_r3p + ((size_t)b*S_ + t + 9 + side*16)*16 + c3;
                float sum = 0.f;
                #pragma unroll
                for (int i = 0; i < 16; ++i) {
                    float g = rp[i*16];
                    sum += g > 0.f ? g : 0.f;
                }
                fbuf[128 + ws*16 + c3] = sum;
            }
            __syncthreads();

            // ---- 5) combine -> feats, then signal chunk arrival ----
            if (tid < 64) {
                int w = tid >> 4, c3 = tid & 15;
                float sum = fbuf[(w*2    )*16 + c3] + fbuf[(w*2 + 1)*16 + c3]
                          + fbuf[128 + (w*2)*16 + c3] + fbuf[128 + (w*2 + 1)*16 + c3];
                g_feats[(b*T_ + t0 + w)*16 + c3] = sum * 0.02f;
            }
            __syncthreads();
            if (tid == 0) {
                __threadfence();
                atomicAdd(&g_done[b*8 + it], 1);
            }
        }
        return;
    }

    // ==================== LSTM roles (blocks 0..47) ====================
    float* hsm    = sm;          // 64
    float* acts   = sm + 64;     // 256
    float* featsm = sm + 320;    // 2*16
    float* h1c    = sm + 352;    // 512 (mid) / zsm 32 (consumer)

    if (blockIdx.x < 16) {
        // ============ producer: layer0 recurrence + inline pre0 (feats consumed live) ============
        const int b = blockIdx.x;
        unsigned long long w0[32], w0i[8];
        {
            const float4* r0 = (const float4*)(whh0 + tid*64);
            #pragma unroll
            for (int q = 0; q < 16; ++q) {
                float4 a = r0[q]; w0[2*q] = pk2(a.x, a.y); w0[2*q+1] = pk2(a.z, a.w);
            }
            const float4* ri = (const float4*)(wih0 + tid*16);
            #pragma unroll
            for (int q = 0; q < 4; ++q) {
                float4 a = ri[q]; w0i[2*q] = pk2(a.x, a.y); w0i[2*q+1] = pk2(a.z, a.w);
            }
        }
        const float bias0v = bih0[tid] + bhh0[tid];
        const float* featsB = g_feats + (size_t)b * T_ * 16;
        float* h1B = g_h1 + (size_t)b * T_ * 64;
        float cst = 0.f;
        if (tid < 64) hsm[tid] = 0.f;

        // wait for first feats chunk from bnd
        if (tid == 0) {
            while (acqload(&g_done[b*8]) < 64) __nanosleep(1024);
        }
        __syncthreads();
        // stage feats(0), feats(1)
        if (tid < 8) {
            int w = tid >> 2, l = tid & 3;
            ((float4*)(featsm + w*16))[l] = ((const float4*)(featsB + w*16))[l];
        }
        __syncthreads();
        // gates0(0) = bias0 + wih0 . feats(0)
        float pg;
        {
            unsigned long long e0 = 0ull, e1 = 0ull;
            const ulonglong2* fq = (const ulonglong2*)featsm;
            #pragma unroll
            for (int q = 0; q < 4; ++q) {
                ulonglong2 fv = fq[q];
                fma2(e0, w0i[2*q],   fv.x);
                fma2(e1, w0i[2*q+1], fv.y);
            }
            float2 f0 = upk2(e0), f1 = upk2(e1);
            pg = bias0v + (f0.x + f0.y) + (f1.x + f1.y);
        }
        acts[tid] = gact(tid, pg);
        float4 r4;
        if (tid >= 128 && tid < 132) {
            r4 = ((const float4*)(featsB + 2*16))[tid - 128];   // feats(2)
        }
        __syncthreads();

        for (int t = 0; t < T_; ++t) {
            // phase 2: state update + h1 publish + feats staging
            if (tid < 64) {
                float c_ = acts[64 + tid]*cst + acts[tid]*acts[128 + tid];
                cst = c_;
                float h = acts[192 + tid]*tanhq(c_);
                hsm[tid] = h;
                h1B[t*64 + tid] = h;
            } else if (tid == 64 && (t & 3) == 0 && t) {
                relstore(&g_flag0[b], t);        // h1(0..t-1) visible
            } else if (tid >= 128 && tid < 132) {
                int l = tid - 128;
                ((float4*)(featsm + ((t + 2) & 1)*16))[l] = r4;   // feats(t+2) -> slot
                int nidx = t + 3;
                int idx = (nidx < T_) ? nidx : T_ - 1;
                if (nidx < T_ && (nidx & 255) == 0) {
                    int ck = nidx >> 8;
                    while (acqload(&g_done[b*8 + ck]) < 64) __nanosleep(256);
                }
                r4 = ((const float4*)(featsB + (size_t)idx*16))[l];
            }
            __syncthreads();
            // phase 3: whh0 dot with h1(t) + wih0 dot with feats(t+1)
            unsigned long long a0 = 0ull, a1 = 0ull;
            const ulonglong2* hp = (const ulonglong2*)hsm;
            #pragma unroll
            for (int q = 0; q < 16; ++q) {
                ulonglong2 hv = hp[q];
                fma2(a0, w0[2*q],   hv.x);
                fma2(a1, w0[2*q+1], hv.y);
            }
            const ulonglong2* fq = (const ulonglong2*)(featsm + ((t + 1) & 1)*16);
            #pragma unroll
            for (int q = 0; q < 4; ++q) {
                ulonglong2 fv = fq[q];
                fma2(a0, w0i[2*q],   fv.x);
                fma2(a1, w0i[2*q+1], fv.y);
            }
            float2 f0 = upk2(a0), f1 = upk2(a1);
            pg = bias0v + (f0.x + f0.y) + (f1.x + f1.y);   // gates0(t+1) pre-act
            acts[tid] = gact(tid, pg);
            __syncthreads();
        }
        if (tid == 0) relstore(&g_flag0[b], T_);
    } else if (blockIdx.x < 32) {
        // ============ mid: pre1 = wih1 @ h1 + bias (chunked GEMM, off critical path) ============
        const int b = blockIdx.x - 16;
        unsigned long long w1[32];
        {
            const float4* r1 = (const float4*)(wih1 + tid*64);
            #pragma unroll
            for (int q = 0; q < 16; ++q) {
                float4 a = r1[q]; w1[2*q] = pk2(a.x, a.y); w1[2*q+1] = pk2(a.z, a.w);
            }
        }
        const float bias1v = bih1[tid] + bhh1[tid];
        const float* h1B = g_h1 + (size_t)b * T_ * 64;
        float* pre1B = g_pre1 + (size_t)b * T_ * 256;
        int flagv = 0;

        for (int c = 0; c < T_/8; ++c) {
            int need = c*8 + 8;
            if (flagv < need) {
                do { flagv = acqload(&g_flag0[b]); if (flagv < need) __nanosleep(128); }
                while (flagv < need);
            }
            for (int i = tid; i < 512; i += 256) h1c[i] = h1B[c*512 + i];
            __syncthreads();
            #pragma unroll
            for (int j = 0; j < 8; ++j) {
                unsigned long long a0 = 0ull, a1 = 0ull;
                const ulonglong2* hp = (const ulonglong2*)(h1c + j*64);
                #pragma unroll
                for (int q = 0; q < 16; ++q) {
                    ulonglong2 hv = hp[q];
                    fma2(a0, w1[2*q],   hv.x);
                    fma2(a1, w1[2*q+1], hv.y);
                }
                float2 f0 = upk2(a0), f1 = upk2(a1);
                pre1B[(c*8 + j)*256 + tid] = bias1v + (f0.x + f0.y) + (f1.x + f1.y);
            }
            __syncthreads();
            if (tid == 0) relstore(&g_flag1[b], c*8 + 8);
        }
    } else {
        // ============ consumer: layer1 recurrence + fused FC head ============
        const int b = blockIdx.x - 32;
        float* zsm = h1c;                        // 32 floats
        unsigned long long w2r[32], wfc[4], w2p[16];
        {
            const float4* r2 = (const float4*)(whh1 + tid*64);
            #pragma unroll
            for (int q = 0; q < 16; ++q) {
                float4 a = r2[q]; w2r[2*q] = pk2(a.x, a.y); w2r[2*q+1] = pk2(a.z, a.w);
            }
            const float4* rf = (const float4*)(fc1w + tid*8);
            #pragma unroll
            for (int q = 0; q < 2; ++q) {
                float4 a = rf[q]; wfc[2*q] = pk2(a.x, a.y); wfc[2*q+1] = pk2(a.z, a.w);
            }
        }
        const float b1r = fc1b[tid >> 3];
        float b2v = 0.f;
        if (tid >= 64 && tid < 66) {
            b2v = fc2b[tid - 64];
            const float4* rw = (const float4*)(fc2w + (tid - 64)*32);
            #pragma unroll
            for (int q = 0; q < 8; ++q) {
                float4 a = rw[q]; w2p[2*q] = pk2(a.x, a.y); w2p[2*q+1] = pk2(a.z, a.w);
            }
        }
        const float* pre1B = g_pre1 + (size_t)b * T_ * 256;
        float* outB = out + (size_t)b * T_ * 2;
        float cst = 0.f;
        int flagv = 0;
        if (tid < 64) hsm[tid] = 0.f;
        while (flagv < 2) { flagv = acqload(&g_flag1[b]); if (flagv < 2) __nanosleep(1024); }
        float cg  = pre1B[tid];                  // gates1(0) pre-act (h2(-1)=0)
        float p1n = pre1B[256 + tid];            // pre1(1)
        acts[tid] = gact(tid, cg);
        __syncthreads();

        for (int t = 0; t < T_; ++t) {
            // phase 2: state update (+ fc2 of step t-1 on threads 64,65)
            if (tid < 64) {
                float c_ = acts[64 + tid]*cst + acts[tid]*acts[128 + tid];
                cst = c_;
                float h = acts[192 + tid]*tanhq(c_);
                hsm[tid] = h;
            } else if (tid < 66 && t > 0) {
                unsigned long long za = 0ull, zb = 0ull;
                const ulonglong2* zq = (const ulonglong2*)zsm;
                #pragma unroll
                for (int q = 0; q < 8; ++q) {
                    ulonglong2 zv = zq[q];
                    fma2(za, w2p[2*q],   zv.x);
                    fma2(zb, w2p[2*q+1], zv.y);
                }
                float2 fa = upk2(za), fb = upk2(zb);
                outB[(t - 1)*2 + (tid - 64)] = b2v + (fa.x + fa.y) + (fb.x + fb.y);
            }
            __syncthreads();
            // phase 3: whh1 dot with h2(t) + fc1 partials on h2(t)
            unsigned long long a0 = 0ull, a1 = 0ull;
            const ulonglong2* hp = (const ulonglong2*)hsm;
            #pragma unroll
            for (int q = 0; q < 16; ++q) {
                ulonglong2 hv = hp[q];
                fma2(a0, w2r[2*q],   hv.x);
                fma2(a1, w2r[2*q+1], hv.y);
            }
            float2 f0 = upk2(a0), f1 = upk2(a1);
            cg = p1n + (f0.x + f0.y) + (f1.x + f1.y);   // gates1(t+1) pre-act
            acts[tid] = gact(tid, cg);
            // fc1: output fi = tid>>3, segment seg = tid&7
            {
                const int seg = tid & 7;
                const ulonglong2* hq = (const ulonglong2*)(hsm + seg*8);
                unsigned long long pa = 0ull, pb = 0ull;
                ulonglong2 hv = hq[0];
                fma2(pa, wfc[0], hv.x);
                fma2(pb, wfc[1], hv.y);
                ulonglong2 hv2 = hq[1];
                fma2(pa, wfc[2], hv2.x);
                fma2(pb, wfc[3], hv2.y);
                float2 pf = upk2(pa), pg2 = upk2(pb);
                float p = (pf.x + pf.y) + (pg2.x + pg2.y);
                p += __shfl_down_sync(0xffffffffu, p, 4, 8);
                p += __shfl_down_sync(0xffffffffu, p, 2, 8);
                p += __shfl_down_sync(0xffffffffu, p, 1, 8);
                if (seg == 0) {
                    float z = p + b1r;
                    zsm[tid >> 3] = z > 0.f ? z : 0.f;
                }
            }
            int tn = (t + 2 < T_) ? t + 2 : T_ - 1;
            if (flagv < tn + 1) {
                do { flagv = acqload(&g_flag1[b]); if (flagv < tn + 1) __nanosleep(64); }
                while (flagv < tn + 1);
            }
            p1n = pre1B[tn*256 + tid];
            __syncthreads();
        }
        // tail: logits for t = T-1 (zsm holds z(T-1))
        if (tid >= 64 && tid < 66) {
            unsigned long long za = 0ull, zb = 0ull;
            const ulonglong2* zq = (const ulonglong2*)zsm;
            #pragma unroll
            for (int q = 0; q < 8; ++q) {
                ulonglong2 zv = zq[q];
                fma2(za, w2p[2*q],   zv.x);
                fma2(zb, w2p[2*q+1], zv.y);
            }
            float2 fa = upk2(za), fb = upk2(zb);
            outB[(T_ - 1)*2 + (tid - 64)] = b2v + (fa.x + fa.y) + (fb.x + fb.y);
        }
    }
}

// ---------------- launch ----------------
extern "C" void kernel_launch(void* const* d_in, const int* in_sizes, int n_in,
                              void* d_out, int out_size)
{
    const float* x     = (const float*)d_in[0];
    const float* c1w   = (const float*)d_in[1];
    const float* c1b   = (const float*)d_in[2];
    const float* bn1g  = (const float*)d_in[3];
    const float* bn1b  = (const float*)d_in[4];
    const float* bn1m  = (const float*)d_in[5];
    const float* bn1v  = (const float*)d_in[6];
    const float* c2w   = (const float*)d_in[7];
    const float* c2b   = (const float*)d_in[8];
    const float* bn2g  = (const float*)d_in[9];
    const float* bn2b  = (const float*)d_in[10];
    const float* bn2m  = (const float*)d_in[11];
    const float* bn2v  = (const float*)d_in[12];
    const float* c3w   = (const float*)d_in[13];
    const float* c3b   = (const float*)d_in[14];
    const float* bn3g  = (const float*)d_in[15];
    const float* bn3b  = (const float*)d_in[16];
    const float* bn3m  = (const float*)d_in[17];
    const float* bn3v  = (const float*)d_in[18];
    const float* wih0  = (const float*)d_in[19];
    const float* whh0  = (const float*)d_in[20];
    const float* bih0  = (const float*)d_in[21];
    const float* bhh0  = (const float*)d_in[22];
    const float* wih1  = (const float*)d_in[23];
    const float* whh1  = (const float*)d_in[24];
    const float* bih1  = (const float*)d_in[25];
    const float* bhh1  = (const float*)d_in[26];
    const float* fc1w  = (const float*)d_in[27];
    const float* fc1b  = (const float*)d_in[28];
    const float* fc2w  = (const float*)d_in[29];
    const float* fc2b  = (const float*)d_in[30];

    cudaFuncSetAttribute(convA_kernel, cudaFuncAttributeMaxDynamicSharedMemorySize,
                         CA_SMEM_FLOATS * 4);
    cudaFuncSetAttribute(bnd_lstm_kernel, cudaFuncAttributeMaxDynamicSharedMemorySize,
                         BND_SMEM_FLOATS * 4);

    // Phase A: merged global conv stack (also resets pipeline flags)
    convA_kernel<<<dim3(33, B_), 256, CA_SMEM_FLOATS * 4>>>(
        x, c1w, c1b, bn1g, bn1b, bn1m, bn1v,
        c2w, c2b, bn2g, bn2b, bn2m, bn2v,
        c3w, c3b, bn3g, bn3b, bn3m, bn3v);

    // Fused Phase B + LSTM + FC: lstm CTAs wave-1 resident, bnd CTAs fill the chip.
    bnd_lstm_kernel<<<48 + NBND, 256, BND_SMEM_FLOATS * 4>>>(
        x, c1w, c1b, bn1g, bn1b, bn1m, bn1v,
        c2w, bn2g, bn2v, c3w, bn3g, bn3v,
        wih0, whh0, bih0, bhh0, wih1, whh1, bih1, bhh1,
        fc1w, fc1b, fc2w, fc2b, (float*)d_out);
}

// round 14
// speedup vs baseline: 1.4230x; 1.4230x over previous
#include <cuda_runtime.h>

#define EPSV 1e-5f
#define B_   16
#define T_   2048
#define S_   2112        // padded stride for global conv buffers

// Global buffers:
__device__ __align__(128) float g_r1 [B_*64*S_];
__device__ __align__(128) float g_r2p[B_*S_*32];
__device__ __align__(128) float g_r3p[B_*S_*16];
__device__ __align__(128) float g_feats[B_*T_*16];
__device__ __align__(128) float g_h1  [B_*T_*64];    // h1 stream (producer -> mid)
__device__ __align__(128) float g_pre1[B_*T_*256];   // layer1 input projection (mid -> consumer)
__device__ __align__(128) float g_h[B_*T_*64];       // h2 (fc input)
__device__ int g_done[B_*8];                         // bnd chunk arrival counters (64 each)
__device__ int g_flag0[B_];
__device__ int g_flag1[B_];

// ======================= Phase A: merged global conv stack =======================
// XP[i] = x[i-49] for 49<=i<=2096 else 0.
// One CTA per (u-block of 64, batch): conv1 halo in smem -> conv2(+4 halo) -> conv3.
#define CA_SMEM_FLOATS 25216

__global__ void __launch_bounds__(256, 2) convA_kernel(
    const float* __restrict__ x,
    const float* __restrict__ c1w, const float* __restrict__ c1b,
    const float* __restrict__ g1, const float* __restrict__ b1p,
    const float* __restrict__ m1, const float* __restrict__ v1,
    const float* __restrict__ c2w, const float* __restrict__ c2b,
    const float* __restrict__ g2, const float* __restrict__ b2p,
    const float* __restrict__ m2, const float* __restrict__ v2,
    const float* __restrict__ c3w, const float* __restrict__ c3b,
    const float* __restrict__ g3, const float* __restrict__ b3p,
    const float* __restrict__ m3, const float* __restrict__ v3)
{
    extern __shared__ float sm[];
    float* w1s = sm;               // 576
    float* w2s = sm + 576;         // 14336  [(c1*7+k)*32 + c2]
    float* w3s = sm + 14912;       // 2560   [(c2*5+k)*16 + c3]
    float* s1  = sm + 17472; float* e1 = sm + 17536;
    float* s2  = sm + 17600; float* e2 = sm + 17632;
    float* s3  = sm + 17664; float* e3 = sm + 17680;
    float* xw  = sm + 17696;       // 84
    float* r1t = sm + 17792;       // 64*80
    float* r2t = sm + 22912;       // 32*72

    const int tid = threadIdx.x;
    const int b = blockIdx.y;
    const int u0 = blockIdx.x * 64;

    if (blockIdx.x == 0 && b == 0) {             // reset pipeline flags each replay
        if (tid < B_*8) g_done[tid] = 0;
        else if (tid < B_*8 + B_) g_flag0[tid - B_*8] = 0;
        else if (tid < B_*8 + 2*B_) g_flag1[tid - B_*8 - B_] = 0;
    }

    for (int i = tid; i < 576; i += 256) w1s[i] = c1w[i];
    for (int i = tid; i < 14336; i += 256) {
        int c2 = i / 448; int r = i % 448; int c1 = r / 7; int k = r % 7;
        w2s[(c1*7 + k)*32 + c2] = c2w[i];
    }
    for (int i = tid; i < 2560; i += 256) {
        int c3 = i / 160; int r = i % 160; int cc = r / 5; int k = r % 5;
        w3s[(cc*5 + k)*16 + c3] = c3w[i];
    }
    if (tid < 64) {
        float s = g1[tid] * rsqrtf(v1[tid] + EPSV);
        s1[tid] = s; e1[tid] = (c1b[tid] - m1[tid]) * s + b1p[tid];
    } else if (tid < 96) {
        int c = tid - 64;
        float s = g2[c] * rsqrtf(v2[c] + EPSV);
        s2[c] = s; e2[c] = (c2b[c] - m2[c]) * s + b2p[c];
    } else if (tid < 112) {
        int c = tid - 96;
        float s = g3[c] * rsqrtf(v3[c] + EPSV);
        s3[c] = s; e3[c] = (c3b[c] - m3[c]) * s + b3p[c];
    } else if (tid >= 128 && tid < 211) {
        int j = tid - 128;                        // xw[j] = XP[u0-9+j], j<83
        int i = u0 - 9 + j;
        xw[j] = (i >= 49 && i <= 2096) ? x[b*2048 + i - 49] : 0.f;
    }
    __syncthreads();

    // ---- conv1: 64 ch x 74 positions (halo for conv2+conv3) ----
    for (int idx = tid; idx < 64*74; idx += 256) {
        int c = idx / 74, i = idx - (idx / 74) * 74;
        float acc = 0.f;
        #pragma unroll
        for (int k = 0; k < 9; ++k) acc += w1s[c*9 + k] * xw[i + k];
        float r = acc * s1[c] + e1[c];
        r = r > 0.f ? r : 0.f;
        r1t[c*80 + i] = r;
        int u = u0 + i;
        if (i < 64 && u <= 2106) g_r1[(b*64 + c)*S_ + u] = r;
    }
    __syncthreads();

    // ---- conv2: 32 ch x 68 positions (4-pos halo for conv3) ----
    {
        const int c2 = tid & 31, slot = tid >> 5;   // 8 slots x 9 positions
        float acc[9];
        #pragma unroll
        for (int j = 0; j < 9; ++j) acc[j] = 0.f;
        for (int c1 = 0; c1 < 64; ++c1) {
            const float* rp = r1t + c1*80 + slot*9;
            float v[15];
            #pragma unroll
            for (int i = 0; i < 15; ++i) v[i] = rp[i];
            const float* wp = w2s + c1*224 + c2;
            #pragma unroll
            for (int k = 0; k < 7; ++k) {
                float wv = wp[k*32];
                #pragma unroll
                for (int j = 0; j < 9; ++j) acc[j] += wv * v[k + j];
            }
        }
        float ss = s2[c2], bb = e2[c2];
        #pragma unroll
        for (int j = 0; j < 9; ++j) {
            int i = slot*9 + j;
            if (i < 68) {
                float pre = acc[j] * ss + bb;
                r2t[c2*72 + i] = pre > 0.f ? pre : 0.f;
                int u = u0 + i;
                if (i < 64 && u <= 2100)
                    g_r2p[((size_t)b*S_ + u)*32 + c2] = pre;   // PRE-act, chan-last
            }
        }
    }
    __syncthreads();

    // ---- conv3: 16 ch x 64 positions ----
    {
        const int c3 = tid & 15, slot = tid >> 4;   // 16 slots x 4 positions
        float acc[4] = {0.f, 0.f, 0.f, 0.f};
        for (int cc = 0; cc < 32; ++cc) {
            const float* rp = r2t + cc*72 + slot*4;
            float v[8];
            #pragma unroll
            for (int i = 0; i < 8; ++i) v[i] = rp[i];
            const float* wp = w3s + cc*80 + c3;
            #pragma unroll
            for (int k = 0; k < 5; ++k) {
                float wv = wp[k*16];
                #pragma unroll
                for (int j = 0; j < 4; ++j) acc[j] += wv * v[k + j];
            }
        }
        float ss = s3[c3], bb = e3[c3];
        #pragma unroll
        for (int j = 0; j < 4; ++j) {
            int u = u0 + slot*4 + j;
            if (u <= 2096)
                g_r3p[((size_t)b*S_ + u)*16 + c3] = acc[j] * ss + bb;   // PRE-act, chan-last
        }
    }
}

// ======================= Fused Phase B + LSTM (single launch, overlap by co-residency) =====
// grid 1072: blocks 0..15 producers, 16..31 mid, 32..47 consumers, 48..1071 bnd.
// bnd CTAs never wait; lstm CTAs at low indices -> wave-1 resident. Deadlock-free.
#define BND_SMEM_FLOATS (14336 + 2560 + 576 + 176 + 64 + 4096 + 3072 + 256)
#define NBND  1024
#define NGRP  8

__device__ __forceinline__ float sigf(float x)  { return __fdividef(1.f, 1.f + __expf(-x)); }
__device__ __forceinline__ float tanhq(float x) { return __fdividef(2.f, 1.f + __expf(-2.f*x)) - 1.f; }

__device__ __forceinline__ unsigned long long pk2(float a, float b) {
    unsigned long long r;
    asm("mov.b64 %0, {%1, %2};" : "=l"(r) : "f"(a), "f"(b));
    return r;
}
__device__ __forceinline__ void fma2(unsigned long long& d,
                                     unsigned long long a, unsigned long long b) {
    asm("fma.rn.f32x2 %0, %1, %2, %0;" : "+l"(d) : "l"(a), "l"(b));
}
__device__ __forceinline__ float2 upk2(unsigned long long v) {
    float2 f;
    asm("mov.b64 {%0, %1}, %2;" : "=f"(f.x), "=f"(f.y) : "l"(v));
    return f;
}
__device__ __forceinline__ void relstore(int* p, int v) {
    asm volatile("st.release.gpu.global.s32 [%0], %1;" :: "l"(p), "r"(v) : "memory");
}
__device__ __forceinline__ int acqload(const int* p) {
    int v;
    asm volatile("ld.acquire.gpu.global.s32 %0, [%1];" : "=r"(v) : "l"(p) : "memory");
    return v;
}
__device__ __forceinline__ float gact(int g, float v) {
    return ((g >> 6) == 2) ? tanhq(v) : sigf(v);   // gate order: i, f, g(tanh), o
}

__global__ void __launch_bounds__(256, 2) bnd_lstm_kernel(
    const float* __restrict__ x,
    const float* __restrict__ c1w, const float* __restrict__ c1b,
    const float* __restrict__ g1, const float* __restrict__ b1p,
    const float* __restrict__ m1, const float* __restrict__ v1,
    const float* __restrict__ c2w,
    const float* __restrict__ g2, const float* __restrict__ v2,
    const float* __restrict__ c3w,
    const float* __restrict__ g3, const float* __restrict__ v3,
    const float* __restrict__ wih0, const float* __restrict__ whh0,
    const float* __restrict__ bih0, const float* __restrict__ bhh0,
    const float* __restrict__ wih1, const float* __restrict__ whh1,
    const float* __restrict__ bih1, const float* __restrict__ bhh1)
{
    extern __shared__ float sm[];
    const int tid = threadIdx.x;

    if (blockIdx.x >= 48) {
        // ==================== bnd: boundary corrections -> feats ====================
        float* w2s    = sm;               // 14336
        float* w3s    = sm + 14336;       // 2560
        float* w1s    = sm + 16896;       // 576
        float* s1s    = sm + 17472;       // 64
        float* e1s    = sm + 17536;       // 64
        float* s2s    = sm + 17600;       // 32
        float* s3s    = sm + 17632;       // 16 (+pad to 17648)
        float* xs     = sm + 17648;       // 64
        float* dstage = sm + 17712;       // 4096
        float* stage3 = sm + 21808;       // 3072
        float* fbuf   = sm + 24880;       // 256

        const int bid = blockIdx.x - 48;
        const int b  = bid >> 6;          // batch
        const int jj = bid & 63;          // CTA slot within batch

        for (int i = tid; i < 14336; i += 256) {
            int c2 = i / 448; int r = i % 448; int c1 = r / 7; int k = r % 7;
            w2s[(c1*7 + k)*32 + c2] = c2w[i];
        }
        for (int i = tid; i < 2560; i += 256) {
            int c3 = i / 160; int r = i % 160; int cc = r / 5; int k = r % 5;
            w3s[(cc*5 + k)*16 + c3] = c3w[i];
        }
        for (int i = tid; i < 576; i += 256) w1s[i] = c1w[i];
        if (tid < 64) {
            float s = g1[tid] * rsqrtf(v1[tid] + EPSV);
            s1s[tid] = s; e1s[tid] = (c1b[tid] - m1[tid]) * s + b1p[tid];
        } else if (tid < 96) {
            int c = tid - 64;
            s2s[c] = g2[c] * rsqrtf(v2[c] + EPSV);
        } else if (tid < 112) {
            int c = tid - 96;
            s3s[c] = g3[c] * rsqrtf(v3[c] + EPSV);
        }
        __syncthreads();

        for (int it = 0; it < NGRP; ++it) {
            const int t0 = ((it << 6) + jj) * 4;

            // ---- 1) stage x values ----
            if (tid < 64) {
                int w = tid >> 4, r = tid & 15;
                int side = r >> 3, j = r & 7;
                int i = t0 + w + (side ? 42 + j : j);
                float v = (i >= 49 && i <= 2096) ? x[b*2048 + i - 49] : 0.f;
                xs[side*32 + w*8 + j] = v;
            }
            __syncthreads();

            // ---- 2) stage delta1 ----
            for (int s = tid; s < 4096; s += 256) {
                int qi = s & 7, c1 = (s >> 3) & 63, side = (s >> 9) & 1, w = s >> 10;
                int t = t0 + w;
                float val = 0.f;
                if (qi < 7) {
                    if (side == 0) {
                        float gl = g_r1[(b*64 + c1)*S_ + t + qi + 2];
                        if (qi < 3) val = -gl;
                        else {
                            int q = qi - 3;
                            float pre = 0.f;
                            #pragma unroll
                            for (int k = 0; k < 9; ++k)
                                if (k >= 4 - q) pre += w1s[c1*9 + k] * xs[w*8 + q - 4 + k];
                            float rv = pre * s1s[c1] + e1s[c1];
                            val = (rv > 0.f ? rv : 0.f) - gl;
                        }
                    } else {
                        float gl = g_r1[(b*64 + c1)*S_ + t + 51 + qi];
                        if (qi >= 4) val = -gl;
                        else {
                            int q = 46 + qi;
                            float pre = 0.f;
                            #pragma unroll
                            for (int k = 0; k < 9; ++k)
                                if (k <= 53 - q) pre += w1s[c1*9 + k] * xs[32 + w*8 + qi + k];
                            float rv = pre * s1s[c1] + e1s[c1];
                            val = (rv > 0.f ? rv : 0.f) - gl;
                        }
                    }
                }
                dstage[s] = val;
            }
            __syncthreads();

            // ---- 3) conv2 correction -> stage3 ----
            {
                const int c2 = tid & 31, side = (tid >> 5) & 1, w = tid >> 6;
                const int t = t0 + w;
                float acc[7];
                #pragma unroll
                for (int p = 0; p < 7; ++p) acc[p] = 0.f;

                for (int c1 = 0; c1 < 64; ++c1) {
                    const float* dp = dstage + ((w*2 + side)*64 + c1)*8;
                    float4 A = *(const float4*)dp;
                    float4 Bv = *(const float4*)(dp + 4);
                    float d[8] = {A.x, A.y, A.z, A.w, Bv.x, Bv.y, Bv.z, Bv.w};
                    const float* wp = w2s + c1*224 + c2;
                    float wk[7];
                    #pragma unroll
                    for (int k = 0; k < 7; ++k) wk[k] = wp[k*32];
                    if (side == 0) {
                        #pragma unroll
                        for (int p = 0; p < 7; ++p)
                            #pragma unroll
                            for (int k = 0; k < 7; ++k)
                                if (k + p <= 6) acc[p] += wk[k] * d[p + k];
                    } else {
                        #pragma unroll
                        for (int p = 0; p < 7; ++p)
                            #pragma unroll
                            for (int k = 0; k < 7; ++k)
                                if (k >= 6 - p) acc[p] += wk[k] * d[p + k - 6];
                    }
                }

                const float s2v = s2s[c2];
                float* sp = stage3 + ((w*2 + side)*32 + c2)*12;
                const float* gpb = g_r2p + ((size_t)b*S_ + t)*32 + c2;
                if (side == 0) {
                    #pragma unroll
                    for (int p = 0; p < 7; ++p) {
                        float gpre = gpb[(p + 2)*32];
                        float pre = gpre + s2v * acc[p];
                        sp[2 + p] = (pre > 0.f ? pre : 0.f) - (gpre > 0.f ? gpre : 0.f);
                    }
                    float e0 = gpb[0], e1v = gpb[32];
                    sp[0] = -(e0 > 0.f ? e0 : 0.f);
                    sp[1] = -(e1v > 0.f ? e1v : 0.f);
                } else {
                    #pragma unroll
                    for (int p = 0; p < 7; ++p) {
                        float gpre = gpb[(45 + p)*32];
                        float pre = gpre + s2v * acc[p];
                        sp[p] = (pre > 0.f ? pre : 0.f) - (gpre > 0.f ? gpre : 0.f);
                    }
                    float e0 = gpb[52*32], e1v = gpb[53*32];
                    sp[7] = -(e0 > 0.f ? e0 : 0.f);
                    sp[8] = -(e1v > 0.f ? e1v : 0.f);
                }
                sp[9] = 0.f; sp[10] = 0.f; sp[11] = 0.f;
            }
            __syncthreads();

            // ---- 4) conv3 correction + interior sums ----
            if (tid < 128) {
                const int c3 = tid & 15, ws = tid >> 4;
                const int side = ws & 1, w = ws >> 1;
                const int t = t0 + w;
                float acc[9];
                #pragma unroll
                for (int p = 0; p < 9; ++p) acc[p] = 0.f;

                for (int c2 = 0; c2 < 32; ++c2) {
                    const float* dp = stage3 + (ws*32 + c2)*12;
                    float4 A = *(const float4*)dp;
                    float4 Bv = *(const float4*)(dp + 4);
                    float C = dp[8];
                    float d[9] = {A.x, A.y, A.z, A.w, Bv.x, Bv.y, Bv.z, Bv.w, C};
                    const float* wp = w3s + c2*80 + c3;
                    float wk[5];
                    #pragma unroll
                    for (int k = 0; k < 5; ++k) wk[k] = wp[k*16];
                    if (side == 0) {
                        #pragma unroll
                        for (int p = 0; p < 9; ++p)
                            #pragma unroll
                            for (int k = 0; k < 5; ++k)
                                if (p + k <= 8) acc[p] += wk[k] * d[p + k];
                    } else {
                        #pragma unroll
                        for (int p = 0; p < 9; ++p)
                            #pragma unroll
                            for (int k = 0; k < 5; ++k)
                                if (k >= 4 - p) acc[p] += wk[k] * d[p + k - 4];
                    }
                }

                float sum = 0.f;
                const float s3v = s3s[c3];
                const float* rp = g_r3p + ((size_t)b*S_ + t)*16 + c3;
                #pragma unroll
                for (int j = 0; j < 9; ++j) {
                    int P = side ? 41 + j : j;
                    float pre = rp[P*16] + s3v * acc[j];
                    sum += pre > 0.f ? pre : 0.f;
                }
                fbuf[ws*16 + c3] = sum;
            } else {
                const int tt = tid - 128;
                const int c3 = tt & 15, ws = tt >> 4;
                const int side = ws & 1, w = ws >> 1;
                const int t = t0 + w;
                const float* rp = g_r3p + ((size_t)b*S_ + t + 9 + side*16)*16 + c3;
                float sum = 0.f;
                #pragma unroll
                for (int i = 0; i < 16; ++i) {
                    float g = rp[i*16];
                    sum += g > 0.f ? g : 0.f;
                }
                fbuf[128 + ws*16 + c3] = sum;
            }
            __syncthreads();

            // ---- 5) combine -> feats, then signal chunk arrival ----
            if (tid < 64) {
                int w = tid >> 4, c3 = tid & 15;
                float sum = fbuf[(w*2    )*16 + c3] + fbuf[(w*2 + 1)*16 + c3]
                          + fbuf[128 + (w*2)*16 + c3] + fbuf[128 + (w*2 + 1)*16 + c3];
                g_feats[(b*T_ + t0 + w)*16 + c3] = sum * 0.02f;
            }
            __syncthreads();
            if (tid == 0) {
                __threadfence();
                atomicAdd(&g_done[b*8 + it], 1);
            }
        }
        return;
    }

    // ==================== LSTM roles (blocks 0..47) ====================
    float* hsm    = sm;          // 64
    float* acts   = sm + 64;     // 256
    float* featsm = sm + 320;    // 2*16
    float* h1c    = sm + 352;    // 512 (mid only)

    if (blockIdx.x < 16) {
        // ============ producer: layer0 recurrence + inline pre0 (feats consumed live) ============
        const int b = blockIdx.x;
        unsigned long long w0[32], w0i[8];
        {
            const float4* r0 = (const float4*)(whh0 + tid*64);
            #pragma unroll
            for (int q = 0; q < 16; ++q) {
                float4 a = r0[q]; w0[2*q] = pk2(a.x, a.y); w0[2*q+1] = pk2(a.z, a.w);
            }
            const float4* ri = (const float4*)(wih0 + tid*16);
            #pragma unroll
            for (int q = 0; q < 4; ++q) {
                float4 a = ri[q]; w0i[2*q] = pk2(a.x, a.y); w0i[2*q+1] = pk2(a.z, a.w);
            }
        }
        const float bias0v = bih0[tid] + bhh0[tid];
        const float* featsB = g_feats + (size_t)b * T_ * 16;
        float* h1B = g_h1 + (size_t)b * T_ * 64;
        float cst = 0.f;
        if (tid < 64) hsm[tid] = 0.f;

        // wait for first feats chunk from bnd
        if (tid == 0) {
            while (acqload(&g_done[b*8]) < 64) __nanosleep(1024);
        }
        __syncthreads();
        // stage feats(0), feats(1)
        if (tid < 8) {
            int w = tid >> 2, l = tid & 3;
            ((float4*)(featsm + w*16))[l] = ((const float4*)(featsB + w*16))[l];
        }
        __syncthreads();
        // gates0(0) = bias0 + wih0 . feats(0)
        float pg;
        {
            unsigned long long e0 = 0ull, e1 = 0ull;
            const ulonglong2* fq = (const ulonglong2*)featsm;
            #pragma unroll
            for (int q = 0; q < 4; ++q) {
                ulonglong2 fv = fq[q];
                fma2(e0, w0i[2*q],   fv.x);
                fma2(e1, w0i[2*q+1], fv.y);
            }
            float2 f0 = upk2(e0), f1 = upk2(e1);
            pg = bias0v + (f0.x + f0.y) + (f1.x + f1.y);
        }
        acts[tid] = gact(tid, pg);
        float4 r4;
        if (tid >= 128 && tid < 132) {
            r4 = ((const float4*)(featsB + 2*16))[tid - 128];   // feats(2)
        }
        __syncthreads();

        for (int t = 0; t < T_; ++t) {
            // phase 2: state update + h1 publish + feats staging
            if (tid < 64) {
                float c_ = acts[64 + tid]*cst + acts[tid]*acts[128 + tid];
                cst = c_;
                float h = acts[192 + tid]*tanhq(c_);
                hsm[tid] = h;
                h1B[t*64 + tid] = h;
            } else if (tid == 64 && (t & 3) == 0 && t) {
                relstore(&g_flag0[b], t);        // h1(0..t-1) visible
            } else if (tid >= 128 && tid < 132) {
                int l = tid - 128;
                ((float4*)(featsm + ((t + 2) & 1)*16))[l] = r4;   // feats(t+2) -> slot
                int nidx = t + 3;
                int idx = (nidx < T_) ? nidx : T_ - 1;
                if (nidx < T_ && (nidx & 255) == 0) {
                    int ck = nidx >> 8;
                    while (acqload(&g_done[b*8 + ck]) < 64) __nanosleep(256);
                }
                r4 = ((const float4*)(featsB + (size_t)idx*16))[l];
            }
            __syncthreads();
            // phase 3: whh0 dot with h1(t) + wih0 dot with feats(t+1)
            unsigned long long a0 = 0ull, a1 = 0ull;
            const ulonglong2* hp = (const ulonglong2*)hsm;
            #pragma unroll
            for (int q = 0; q < 16; ++q) {
                ulonglong2 hv = hp[q];
                fma2(a0, w0[2*q],   hv.x);
                fma2(a1, w0[2*q+1], hv.y);
            }
            const ulonglong2* fq = (const ulonglong2*)(featsm + ((t + 1) & 1)*16);
            #pragma unroll
            for (int q = 0; q < 4; ++q) {
                ulonglong2 fv = fq[q];
                fma2(a0, w0i[2*q],   fv.x);
                fma2(a1, w0i[2*q+1], fv.y);
            }
            float2 f0 = upk2(a0), f1 = upk2(a1);
            pg = bias0v + (f0.x + f0.y) + (f1.x + f1.y);   // gates0(t+1) pre-act
            acts[tid] = gact(tid, pg);
            __syncthreads();
        }
        if (tid == 0) relstore(&g_flag0[b], T_);
    } else if (blockIdx.x < 32) {
        // ============ mid: pre1 = wih1 @ h1 + bias (chunked GEMM, off critical path) ============
        const int b = blockIdx.x - 16;
        unsigned long long w1[32];
        {
            const float4* r1 = (const float4*)(wih1 + tid*64);
            #pragma unroll
            for (int q = 0; q < 16; ++q) {
                float4 a = r1[q]; w1[2*q] = pk2(a.x, a.y); w1[2*q+1] = pk2(a.z, a.w);
            }
        }
        const float bias1v = bih1[tid] + bhh1[tid];
        const float* h1B = g_h1 + (size_t)b * T_ * 64;
        float* pre1B = g_pre1 + (size_t)b * T_ * 256;
        int flagv = 0;

        for (int c = 0; c < T_/8; ++c) {
            int need = c*8 + 8;
            if (flagv < need) {
                do { flagv = acqload(&g_flag0[b]); if (flagv < need) __nanosleep(128); }
                while (flagv < need);
            }
            for (int i = tid; i < 512; i += 256) h1c[i] = h1B[c*512 + i];
            __syncthreads();
            #pragma unroll
            for (int j = 0; j < 8; ++j) {
                unsigned long long a0 = 0ull, a1 = 0ull;
                const ulonglong2* hp = (const ulonglong2*)(h1c + j*64);
                #pragma unroll
                for (int q = 0; q < 16; ++q) {
                    ulonglong2 hv = hp[q];
                    fma2(a0, w1[2*q],   hv.x);
                    fma2(a1, w1[2*q+1], hv.y);
                }
                float2 f0 = upk2(a0), f1 = upk2(a1);
                pre1B[(c*8 + j)*256 + tid] = bias1v + (f0.x + f0.y) + (f1.x + f1.y);
            }
            __syncthreads();
            if (tid == 0) relstore(&g_flag1[b], c*8 + 8);
        }
    } else {
        // ============ consumer: layer1 recurrence ============
        const int b = blockIdx.x - 32;
        unsigned long long w2r[32];
        {
            const float4* r2 = (const float4*)(whh1 + tid*64);
            #pragma unroll
            for (int q = 0; q < 16; ++q) {
                float4 a = r2[q]; w2r[2*q] = pk2(a.x, a.y); w2r[2*q+1] = pk2(a.z, a.w);
            }
        }
        const float* pre1B = g_pre1 + (size_t)b * T_ * 256;
        float* hB = g_h + (size_t)b * T_ * 64;
        float cst = 0.f;
        int flagv = 0;
        if (tid < 64) hsm[tid] = 0.f;
        while (flagv < 2) { flagv = acqload(&g_flag1[b]); if (flagv < 2) __nanosleep(1024); }
        float cg  = pre1B[tid];                  // gates1(0) pre-act (h2(-1)=0)
        float p1n = pre1B[256 + tid];            // pre1(1)
        acts[tid] = gact(tid, cg);
        __syncthreads();

        for (int t = 0; t < T_; ++t) {
            // phase 2: state update + h2 store
            if (tid < 64) {
                float c_ = acts[64 + tid]*cst + acts[tid]*acts[128 + tid];
                cst = c_;
                float h = acts[192 + tid]*tanhq(c_);
                hsm[tid] = h;
                hB[t*64 + tid] = h;
            }
            __syncthreads();
            // phase 3: whh1 dot with h2(t)
            unsigned long long a0 = 0ull, a1 = 0ull;
            const ulonglong2* hp = (const ulonglong2*)hsm;
            #pragma unroll
            for (int q = 0; q < 16; ++q) {
                ulonglong2 hv = hp[q];
                fma2(a0, w2r[2*q],   hv.x);
                fma2(a1, w2r[2*q+1], hv.y);
            }
            float2 f0 = upk2(a0), f1 = upk2(a1);
            cg = p1n + (f0.x + f0.y) + (f1.x + f1.y);   // gates1(t+1) pre-act
            acts[tid] = gact(tid, cg);
            int tn = (t + 2 < T_) ? t + 2 : T_ - 1;
            if (flagv < tn + 1) {
                do { flagv = acqload(&g_flag1[b]); if (flagv < tn + 1) __nanosleep(64); }
                while (flagv < tn + 1);
            }
            p1n = pre1B[tn*256 + tid];
            __syncthreads();
        }
    }
}

// ---------------- FC head ----------------
__global__ void __launch_bounds__(256) fc_kernel(
    const float* __restrict__ w1, const float* __restrict__ b1,
    const float* __restrict__ w2, const float* __restrict__ b2,
    float* __restrict__ out)
{
    __shared__ __align__(16) float w1s[2048];
    __shared__ float w2s[64];
    __shared__ float b1s[32];
    int tid = threadIdx.x;
    for (int i = tid; i < 2048; i += 256) w1s[i] = w1[i];
    if (tid < 64) w2s[tid] = w2[tid];
    if (tid < 32) b1s[tid] = b1[tid];
    __syncthreads();

    int gid = blockIdx.x*256 + tid;
    const float4* h4p = (const float4*)(g_h + (size_t)gid * 64);
    float4 h[16];
    #pragma unroll
    for (int q = 0; q < 16; ++q) h[q] = h4p[q];

    float l0 = b2[0], l1 = b2[1];
    #pragma unroll
    for (int i = 0; i < 32; ++i) {
        float acc = b1s[i];
        const float4* wr = (const float4*)(w1s + i*64);
        #pragma unroll
        for (int q = 0; q < 16; ++q) {
            float4 w4 = wr[q];
            acc += w4.x*h[q].x + w4.y*h[q].y + w4.z*h[q].z + w4.w*h[q].w;
        }
        acc = acc > 0.f ? acc : 0.f;
        l0 += w2s[i] * acc;
        l1 += w2s[32 + i] * acc;
    }
    ((float2*)out)[gid] = make_float2(l0, l1);
}

// ---------------- launch ----------------
extern "C" void kernel_launch(void* const* d_in, const int* in_sizes, int n_in,
                              void* d_out, int out_size)
{
    const float* x     = (const float*)d_in[0];
    const float* c1w   = (const float*)d_in[1];
    const float* c1b   = (const float*)d_in[2];
    const float* bn1g  = (const float*)d_in[3];
    const float* bn1b  = (const float*)d_in[4];
    const float* bn1m  = (const float*)d_in[5];
    const float* bn1v  = (const float*)d_in[6];
    const float* c2w   = (const float*)d_in[7];
    const float* c2b   = (const float*)d_in[8];
    const float* bn2g  = (const float*)d_in[9];
    const float* bn2b  = (const float*)d_in[10];
    const float* bn2m  = (const float*)d_in[11];
    const float* bn2v  = (const float*)d_in[12];
    const float* c3w   = (const float*)d_in[13];
    const float* c3b   = (const float*)d_in[14];
    const float* bn3g  = (const float*)d_in[15];
    const float* bn3b  = (const float*)d_in[16];
    const float* bn3m  = (const float*)d_in[17];
    const float* bn3v  = (const float*)d_in[18];
    const float* wih0  = (const float*)d_in[19];
    const float* whh0  = (const float*)d_in[20];
    const float* bih0  = (const float*)d_in[21];
    const float* bhh0  = (const float*)d_in[22];
    const float* wih1  = (const float*)d_in[23];
    const float* whh1  = (const float*)d_in[24];
    const float* bih1  = (const float*)d_in[25];
    const float* bhh1  = (const float*)d_in[26];
    const float* fc1w  = (const float*)d_in[27];
    const float* fc1b  = (const float*)d_in[28];
    const float* fc2w  = (const float*)d_in[29];
    const float* fc2b  = (const float*)d_in[30];

    cudaFuncSetAttribute(convA_kernel, cudaFuncAttributeMaxDynamicSharedMemorySize,
                         CA_SMEM_FLOATS * 4);
    cudaFuncSetAttribute(bnd_lstm_kernel, cudaFuncAttributeMaxDynamicSharedMemorySize,
                         BND_SMEM_FLOATS * 4);

    // Phase A: merged global conv stack (also resets pipeline flags)
    convA_kernel<<<dim3(33, B_), 256, CA_SMEM_FLOATS * 4>>>(
        x, c1w, c1b, bn1g, bn1b, bn1m, bn1v,
        c2w, c2b, bn2g, bn2b, bn2m, bn2v,
        c3w, c3b, bn3g, bn3b, bn3m, bn3v);

    // Fused Phase B + LSTM: lstm CTAs wave-1 resident, bnd CTAs fill the chip.
    bnd_lstm_kernel<<<48 + NBND, 256, BND_SMEM_FLOATS * 4>>>(
        x, c1w, c1b, bn1g, bn1b, bn1m, bn1v,
        c2w, bn2g, bn2v, c3w, bn3g, bn3v,
        wih0, whh0, bih0, bhh0, wih1, whh1, bih1, bhh1);

    // FC head
    fc_kernel<<<(B_ * T_) / 256, 256>>>(fc1w, fc1b, fc2w, fc2b, (float*)d_out);
}

// round 15
// speedup vs baseline: 1.8642x; 1.3100x over previous
#include <cuda_runtime.h>

#define EPSV 1e-5f
#define B_   16
#define T_   2048
#define S_   2112        // padded stride for global conv buffers

// Global buffers:
__device__ __align__(128) float g_r1 [B_*64*S_];
__device__ __align__(128) float g_r2p[B_*S_*32];
__device__ __align__(128) float g_r3p[B_*S_*16];
__device__ __align__(128) float g_feats[B_*T_*16];
__device__ __align__(128) float g_h1  [B_*T_*64];    // h1 stream (producer -> mid)
__device__ __align__(128) float g_pre1[B_*T_*256];   // layer1 input projection (mid -> consumer)
__device__ __align__(128) float g_h[B_*T_*64];       // h2 (fc input)
__device__ int g_done[B_*8];                         // bnd chunk arrival counters (64 each)
__device__ int g_flag0[B_];
__device__ int g_flag1[B_];
__device__ int g_lstm_sm[256];                       // smid -> hosts an lstm CTA
__device__ int g_wq;                                 // bnd work-queue head

// ======================= Phase A: merged global conv stack =======================
// XP[i] = x[i-49] for 49<=i<=2096 else 0.
#define CA_SMEM_FLOATS 25216

__global__ void __launch_bounds__(256, 2) convA_kernel(
    const float* __restrict__ x,
    const float* __restrict__ c1w, const float* __restrict__ c1b,
    const float* __restrict__ g1, const float* __restrict__ b1p,
    const float* __restrict__ m1, const float* __restrict__ v1,
    const float* __restrict__ c2w, const float* __restrict__ c2b,
    const float* __restrict__ g2, const float* __restrict__ b2p,
    const float* __restrict__ m2, const float* __restrict__ v2,
    const float* __restrict__ c3w, const float* __restrict__ c3b,
    const float* __restrict__ g3, const float* __restrict__ b3p,
    const float* __restrict__ m3, const float* __restrict__ v3)
{
    extern __shared__ float sm[];
    float* w1s = sm;               // 576
    float* w2s = sm + 576;         // 14336  [(c1*7+k)*32 + c2]
    float* w3s = sm + 14912;       // 2560   [(c2*5+k)*16 + c3]
    float* s1  = sm + 17472; float* e1 = sm + 17536;
    float* s2  = sm + 17600; float* e2 = sm + 17632;
    float* s3  = sm + 17664; float* e3 = sm + 17680;
    float* xw  = sm + 17696;       // 84
    float* r1t = sm + 17792;       // 64*80
    float* r2t = sm + 22912;       // 32*72

    const int tid = threadIdx.x;
    const int b = blockIdx.y;
    const int u0 = blockIdx.x * 64;

    if (blockIdx.x == 0 && b == 0) {             // reset pipeline state each replay
        g_lstm_sm[tid] = 0;
        if (tid < B_*8) g_done[tid] = 0;
        else if (tid < B_*8 + B_) g_flag0[tid - B_*8] = 0;
        else if (tid < B_*8 + 2*B_) g_flag1[tid - B_*8 - B_] = 0;
        else if (tid == 255) g_wq = 0;
    }

    for (int i = tid; i < 576; i += 256) w1s[i] = c1w[i];
    for (int i = tid; i < 14336; i += 256) {
        int c2 = i / 448; int r = i % 448; int c1 = r / 7; int k = r % 7;
        w2s[(c1*7 + k)*32 + c2] = c2w[i];
    }
    for (int i = tid; i < 2560; i += 256) {
        int c3 = i / 160; int r = i % 160; int cc = r / 5; int k = r % 5;
        w3s[(cc*5 + k)*16 + c3] = c3w[i];
    }
    if (tid < 64) {
        float s = g1[tid] * rsqrtf(v1[tid] + EPSV);
        s1[tid] = s; e1[tid] = (c1b[tid] - m1[tid]) * s + b1p[tid];
    } else if (tid < 96) {
        int c = tid - 64;
        float s = g2[c] * rsqrtf(v2[c] + EPSV);
        s2[c] = s; e2[c] = (c2b[c] - m2[c]) * s + b2p[c];
    } else if (tid < 112) {
        int c = tid - 96;
        float s = g3[c] * rsqrtf(v3[c] + EPSV);
        s3[c] = s; e3[c] = (c3b[c] - m3[c]) * s + b3p[c];
    }
    if (tid >= 128 && tid < 211) {
        int j = tid - 128;                        // xw[j] = XP[u0-9+j], j<83
        int i = u0 - 9 + j;
        xw[j] = (i >= 49 && i <= 2096) ? x[b*2048 + i - 49] : 0.f;
    }
    __syncthreads();

    // ---- conv1: 64 ch x 74 positions (halo for conv2+conv3) ----
    for (int idx = tid; idx < 64*74; idx += 256) {
        int c = idx / 74, i = idx - (idx / 74) * 74;
        float acc = 0.f;
        #pragma unroll
        for (int k = 0; k < 9; ++k) acc += w1s[c*9 + k] * xw[i + k];
        float r = acc * s1[c] + e1[c];
        r = r > 0.f ? r : 0.f;
        r1t[c*80 + i] = r;
        int u = u0 + i;
        if (i < 64 && u <= 2106) g_r1[(b*64 + c)*S_ + u] = r;
    }
    __syncthreads();

    // ---- conv2: 32 ch x 68 positions (4-pos halo for conv3) ----
    {
        const int c2 = tid & 31, slot = tid >> 5;   // 8 slots x 9 positions
        float acc[9];
        #pragma unroll
        for (int j = 0; j < 9; ++j) acc[j] = 0.f;
        for (int c1 = 0; c1 < 64; ++c1) {
            const float* rp = r1t + c1*80 + slot*9;
            float v[15];
            #pragma unroll
            for (int i = 0; i < 15; ++i) v[i] = rp[i];
            const float* wp = w2s + c1*224 + c2;
            #pragma unroll
            for (int k = 0; k < 7; ++k) {
                float wv = wp[k*32];
                #pragma unroll
                for (int j = 0; j < 9; ++j) acc[j] += wv * v[k + j];
            }
        }
        float ss = s2[c2], bb = e2[c2];
        #pragma unroll
        for (int j = 0; j < 9; ++j) {
            int i = slot*9 + j;
            if (i < 68) {
                float pre = acc[j] * ss + bb;
                r2t[c2*72 + i] = pre > 0.f ? pre : 0.f;
                int u = u0 + i;
                if (i < 64 && u <= 2100)
                    g_r2p[((size_t)b*S_ + u)*32 + c2] = pre;   // PRE-act, chan-last
            }
        }
    }
    __syncthreads();

    // ---- conv3: 16 ch x 64 positions ----
    {
        const int c3 = tid & 15, slot = tid >> 4;   // 16 slots x 4 positions
        float acc[4] = {0.f, 0.f, 0.f, 0.f};
        for (int cc = 0; cc < 32; ++cc) {
            const float* rp = r2t + cc*72 + slot*4;
            float v[8];
            #pragma unroll
            for (int i = 0; i < 8; ++i) v[i] = rp[i];
            const float* wp = w3s + cc*80 + c3;
            #pragma unroll
            for (int k = 0; k < 5; ++k) {
                float wv = wp[k*16];
                #pragma unroll
                for (int j = 0; j < 4; ++j) acc[j] += wv * v[k + j];
            }
        }
        float ss = s3[c3], bb = e3[c3];
        #pragma unroll
        for (int j = 0; j < 4; ++j) {
            int u = u0 + slot*4 + j;
            if (u <= 2096)
                g_r3p[((size_t)b*S_ + u)*16 + c3] = acc[j] * ss + bb;   // PRE-act, chan-last
        }
    }
}

// ======================= Fused Phase B + LSTM (SM-affinity partitioned) =====
// grid 1072: blocks 0..15 producers, 16..31 mid, 32..47 consumers, 48..1071 bnd workers.
// lstm CTAs flag their SM; bnd CTAs on flagged SMs exit; rest pop a global work queue.
#define BND_SMEM_FLOATS (14336 + 2560 + 576 + 176 + 64 + 4096 + 3072 + 256)
#define NBND  1024
#define NUNITS (B_*8*64)     // 8192 group-units, it-major

__device__ __forceinline__ float sigf(float x)  { return __fdividef(1.f, 1.f + __expf(-x)); }
__device__ __forceinline__ float tanhq(float x) { return __fdividef(2.f, 1.f + __expf(-2.f*x)) - 1.f; }

__device__ __forceinline__ unsigned long long pk2(float a, float b) {
    unsigned long long r;
    asm("mov.b64 %0, {%1, %2};" : "=l"(r) : "f"(a), "f"(b));
    return r;
}
__device__ __forceinline__ void fma2(unsigned long long& d,
                                     unsigned long long a, unsigned long long b) {
    asm("fma.rn.f32x2 %0, %1, %2, %0;" : "+l"(d) : "l"(a), "l"(b));
}
__device__ __forceinline__ float2 upk2(unsigned long long v) {
    float2 f;
    asm("mov.b64 {%0, %1}, %2;" : "=f"(f.x), "=f"(f.y) : "l"(v));
    return f;
}
__device__ __forceinline__ void relstore(int* p, int v) {
    asm volatile("st.release.gpu.global.s32 [%0], %1;" :: "l"(p), "r"(v) : "memory");
}
__device__ __forceinline__ int acqload(const int* p) {
    int v;
    asm volatile("ld.acquire.gpu.global.s32 %0, [%1];" : "=r"(v) : "l"(p) : "memory");
    return v;
}
__device__ __forceinline__ int smid() {
    int s;
    asm("mov.u32 %0, %%smid;" : "=r"(s));
    return s;
}
__device__ __forceinline__ float gact(int g, float v) {
    return ((g >> 6) == 2) ? tanhq(v) : sigf(v);   // gate order: i, f, g(tanh), o
}

__global__ void __launch_bounds__(256, 2) bnd_lstm_kernel(
    const float* __restrict__ x,
    const float* __restrict__ c1w, const float* __restrict__ c1b,
    const float* __restrict__ g1, const float* __restrict__ b1p,
    const float* __restrict__ m1, const float* __restrict__ v1,
    const float* __restrict__ c2w,
    const float* __restrict__ g2, const float* __restrict__ v2,
    const float* __restrict__ c3w,
    const float* __restrict__ g3, const float* __restrict__ v3,
    const float* __restrict__ wih0, const float* __restrict__ whh0,
    const float* __restrict__ bih0, const float* __restrict__ bhh0,
    const float* __restrict__ wih1, const float* __restrict__ whh1,
    const float* __restrict__ bih1, const float* __restrict__ bhh1)
{
    extern __shared__ float sm[];
    __shared__ int s_ctl;
    const int tid = threadIdx.x;

    if (blockIdx.x >= 48) {
        // ==================== bnd worker: boundary corrections -> feats ====================
        // SM-affinity: leave lstm-hosting SMs alone.
        if (tid == 0) s_ctl = acqload(&g_lstm_sm[smid()]);
        __syncthreads();
        if (s_ctl) return;

        float* w2s    = sm;               // 14336
        float* w3s    = sm + 14336;       // 2560
        float* w1s    = sm + 16896;       // 576
        float* s1s    = sm + 17472;       // 64
        float* e1s    = sm + 17536;       // 64
        float* s2s    = sm + 17600;       // 32
        float* s3s    = sm + 17632;       // 16 (+pad to 17648)
        float* xs     = sm + 17648;       // 64
        float* dstage = sm + 17712;       // 4096
        float* stage3 = sm + 21808;       // 3072
        float* fbuf   = sm + 24880;       // 256

        for (int i = tid; i < 14336; i += 256) {
            int c2 = i / 448; int r = i % 448; int c1 = r / 7; int k = r % 7;
            w2s[(c1*7 + k)*32 + c2] = c2w[i];
        }
        for (int i = tid; i < 2560; i += 256) {
            int c3 = i / 160; int r = i % 160; int cc = r / 5; int k = r % 5;
            w3s[(cc*5 + k)*16 + c3] = c3w[i];
        }
        for (int i = tid; i < 576; i += 256) w1s[i] = c1w[i];
        if (tid < 64) {
            float s = g1[tid] * rsqrtf(v1[tid] + EPSV);
            s1s[tid] = s; e1s[tid] = (c1b[tid] - m1[tid]) * s + b1p[tid];
        } else if (tid < 96) {
            int c = tid - 64;
            s2s[c] = g2[c] * rsqrtf(v2[c] + EPSV);
        } else if (tid < 112) {
            int c = tid - 96;
            s3s[c] = g3[c] * rsqrtf(v3[c] + EPSV);
        }
        __syncthreads();
        // recheck after staging (~µs) — catches the launch-time race
        if (tid == 0) s_ctl = acqload(&g_lstm_sm[smid()]);
        __syncthreads();
        if (s_ctl) return;

        while (true) {
            if (tid == 0) s_ctl = atomicAdd(&g_wq, 1);
            __syncthreads();
            const int unit = s_ctl;
            if (unit >= NUNITS) break;
            const int it = unit >> 10;           // it-major: prefix order
            const int idx = unit & 1023;
            const int b  = idx >> 6;
            const int jj = idx & 63;
            const int t0 = ((it << 6) + jj) * 4;

            // ---- 1) stage x values ----
            if (tid < 64) {
                int w = tid >> 4, r = tid & 15;
                int side = r >> 3, j = r & 7;
                int i = t0 + w + (side ? 42 + j : j);
                float v = (i >= 49 && i <= 2096) ? x[b*2048 + i - 49] : 0.f;
                xs[side*32 + w*8 + j] = v;
            }
            __syncthreads();

            // ---- 2) stage delta1 ----
            for (int s = tid; s < 4096; s += 256) {
                int qi = s & 7, c1 = (s >> 3) & 63, side = (s >> 9) & 1, w = s >> 10;
                int t = t0 + w;
                float val = 0.f;
                if (qi < 7) {
                    if (side == 0) {
                        float gl = g_r1[(b*64 + c1)*S_ + t + qi + 2];
                        if (qi < 3) val = -gl;
                        else {
                            int q = qi - 3;
                            float pre = 0.f;
                            #pragma unroll
                            for (int k = 0; k < 9; ++k)
                                if (k >= 4 - q) pre += w1s[c1*9 + k] * xs[w*8 + q - 4 + k];
                            float rv = pre * s1s[c1] + e1s[c1];
                            val = (rv > 0.f ? rv : 0.f) - gl;
                        }
                    } else {
                        float gl = g_r1[(b*64 + c1)*S_ + t + 51 + qi];
                        if (qi >= 4) val = -gl;
                        else {
                            int q = 46 + qi;
                            float pre = 0.f;
                            #pragma unroll
                            for (int k = 0; k < 9; ++k)
                                if (k <= 53 - q) pre += w1s[c1*9 + k] * xs[32 + w*8 + qi + k];
                            float rv = pre * s1s[c1] + e1s[c1];
                            val = (rv > 0.f ? rv : 0.f) - gl;
                        }
                    }
                }
                dstage[s] = val;
            }
            __syncthreads();

            // ---- 3) conv2 correction -> stage3 ----
            {
                const int c2 = tid & 31, side = (tid >> 5) & 1, w = tid >> 6;
                const int t = t0 + w;
                float acc[7];
                #pragma unroll
                for (int p = 0; p < 7; ++p) acc[p] = 0.f;

                for (int c1 = 0; c1 < 64; ++c1) {
                    const float* dp = dstage + ((w*2 + side)*64 + c1)*8;
                    float4 A = *(const float4*)dp;
                    float4 Bv = *(const float4*)(dp + 4);
                    float d[8] = {A.x, A.y, A.z, A.w, Bv.x, Bv.y, Bv.z, Bv.w};
                    const float* wp = w2s + c1*224 + c2;
                    float wk[7];
                    #pragma unroll
                    for (int k = 0; k < 7; ++k) wk[k] = wp[k*32];
                    if (side == 0) {
                        #pragma unroll
                        for (int p = 0; p < 7; ++p)
                            #pragma unroll
                            for (int k = 0; k < 7; ++k)
                                if (k + p <= 6) acc[p] += wk[k] * d[p + k];
                    } else {
                        #pragma unroll
                        for (int p = 0; p < 7; ++p)
                            #pragma unroll
                            for (int k = 0; k < 7; ++k)
                                if (k >= 6 - p) acc[p] += wk[k] * d[p + k - 6];
                    }
                }

                const float s2v = s2s[c2];
                float* sp = stage3 + ((w*2 + side)*32 + c2)*12;
                const float* gpb = g_r2p + ((size_t)b*S_ + t)*32 + c2;
                if (side == 0) {
                    #pragma unroll
                    for (int p = 0; p < 7; ++p) {
                        float gpre = gpb[(p + 2)*32];
                        float pre = gpre + s2v * acc[p];
                        sp[2 + p] = (pre > 0.f ? pre : 0.f) - (gpre > 0.f ? gpre : 0.f);
                    }
                    float e0 = gpb[0], e1v = gpb[32];
                    sp[0] = -(e0 > 0.f ? e0 : 0.f);
                    sp[1] = -(e1v > 0.f ? e1v : 0.f);
                } else {
                    #pragma unroll
                    for (int p = 0; p < 7; ++p) {
                        float gpre = gpb[(45 + p)*32];
                        float pre = gpre + s2v * acc[p];
                        sp[p] = (pre > 0.f ? pre : 0.f) - (gpre > 0.f ? gpre : 0.f);
                    }
                    float e0 = gpb[52*32], e1v = gpb[53*32];
                    sp[7] = -(e0 > 0.f ? e0 : 0.f);
                    sp[8] = -(e1v > 0.f ? e1v : 0.f);
                }
                sp[9] = 0.f; sp[10] = 0.f; sp[11] = 0.f;
            }
            __syncthreads();

            // ---- 4) conv3 correction + interior sums ----
            if (tid < 128) {
                const int c3 = tid & 15, ws = tid >> 4;
                const int side = ws & 1, w = ws >> 1;
                const int t = t0 + w;
                float acc[9];
                #pragma unroll
                for (int p = 0; p < 9; ++p) acc[p] = 0.f;

                for (int c2 = 0; c2 < 32; ++c2) {
                    const float* dp = stage3 + (ws*32 + c2)*12;
                    float4 A = *(const float4*)dp;
                    float4 Bv = *(const float4*)(dp + 4);
                    float C = dp[8];
                    float d[9] = {A.x, A.y, A.z, A.w, Bv.x, Bv.y, Bv.z, Bv.w, C};
                    const float* wp = w3s + c2*80 + c3;
                    float wk[5];
                    #pragma unroll
                    for (int k = 0; k < 5; ++k) wk[k] = wp[k*16];
                    if (side == 0) {
                        #pragma unroll
                        for (int p = 0; p < 9; ++p)
                            #pragma unroll
                            for (int k = 0; k < 5; ++k)
                                if (p + k <= 8) acc[p] += wk[k] * d[p + k];
                    } else {
                        #pragma unroll
                        for (int p = 0; p < 9; ++p)
                            #pragma unroll
                            for (int k = 0; k < 5; ++k)
                                if (k >= 4 - p) acc[p] += wk[k] * d[p + k - 4];
                    }
                }

                float sum = 0.f;
                const float s3v = s3s[c3];
                const float* rp = g_r3p + ((size_t)b*S_ + t)*16 + c3;
                #pragma unroll
                for (int j = 0; j < 9; ++j) {
                    int P = side ? 41 + j : j;
                    float pre = rp[P*16] + s3v * acc[j];
                    sum += pre > 0.f ? pre : 0.f;
                }
                fbuf[ws*16 + c3] = sum;
            } else {
                const int tt = tid - 128;
                const int c3 = tt & 15, ws = tt >> 4;
                const int side = ws & 1, w = ws >> 1;
                const int t = t0 + w;
                const float* rp = g_r3p + ((size_t)b*S_ + t + 9 + side*16)*16 + c3;
                float sum = 0.f;
                #pragma unroll
                for (int i = 0; i < 16; ++i) {
                    float g = rp[i*16];
                    sum += g > 0.f ? g : 0.f;
                }
                fbuf[128 + ws*16 + c3] = sum;
            }
            __syncthreads();

            // ---- 5) combine -> feats, then signal unit arrival ----
            if (tid < 64) {
                int w = tid >> 4, c3 = tid & 15;
                float sum = fbuf[(w*2    )*16 + c3] + fbuf[(w*2 + 1)*16 + c3]
                          + fbuf[128 + (w*2)*16 + c3] + fbuf[128 + (w*2 + 1)*16 + c3];
                g_feats[(b*T_ + t0 + w)*16 + c3] = sum * 0.02f;
            }
            __syncthreads();
            if (tid == 0) {
                __threadfence();
                atomicAdd(&g_done[b*8 + it], 1);
            }
            __syncthreads();
        }
        return;
    }

    // ==================== LSTM roles (blocks 0..47) — claim SM first ====================
    if (tid == 0) atomicExch(&g_lstm_sm[smid()], 1);

    float* hsm    = sm;          // 64
    float* acts   = sm + 64;     // 256
    float* featsm = sm + 320;    // 2*16
    float* h1c    = sm + 352;    // 512 (mid only)

    if (blockIdx.x < 16) {
        // ============ producer: layer0 recurrence + inline pre0 (feats consumed live) ============
        const int b = blockIdx.x;
        unsigned long long w0[32], w0i[8];
        {
            const float4* r0 = (const float4*)(whh0 + tid*64);
            #pragma unroll
            for (int q = 0; q < 16; ++q) {
                float4 a = r0[q]; w0[2*q] = pk2(a.x, a.y); w0[2*q+1] = pk2(a.z, a.w);
            }
            const float4* ri = (const float4*)(wih0 + tid*16);
            #pragma unroll
            for (int q = 0; q < 4; ++q) {
                float4 a = ri[q]; w0i[2*q] = pk2(a.x, a.y); w0i[2*q+1] = pk2(a.z, a.w);
            }
        }
        const float bias0v = bih0[tid] + bhh0[tid];
        const float* featsB = g_feats + (size_t)b * T_ * 16;
        float* h1B = g_h1 + (size_t)b * T_ * 64;
        float cst = 0.f;
        if (tid < 64) hsm[tid] = 0.f;

        // wait for first feats chunk from bnd
        if (tid == 0) {
            while (acqload(&g_done[b*8]) < 64) __nanosleep(1024);
        }
        __syncthreads();
        // stage feats(0), feats(1)
        if (tid < 8) {
            int w = tid >> 2, l = tid & 3;
            ((float4*)(featsm + w*16))[l] = ((const float4*)(featsB + w*16))[l];
        }
        __syncthreads();
        // gates0(0) = bias0 + wih0 . feats(0)
        float pg;
        {
            unsigned long long e0 = 0ull, e1 = 0ull;
            const ulonglong2* fq = (const ulonglong2*)featsm;
            #pragma unroll
            for (int q = 0; q < 4; ++q) {
                ulonglong2 fv = fq[q];
                fma2(e0, w0i[2*q],   fv.x);
                fma2(e1, w0i[2*q+1], fv.y);
            }
            float2 f0 = upk2(e0), f1 = upk2(e1);
            pg = bias0v + (f0.x + f0.y) + (f1.x + f1.y);
        }
        acts[tid] = gact(tid, pg);
        float4 r4;
        if (tid >= 128 && tid < 132) {
            r4 = ((const float4*)(featsB + 2*16))[tid - 128];   // feats(2)
        }
        __syncthreads();

        for (int t = 0; t < T_; ++t) {
            // phase 2: state update + h1 publish + feats staging
            if (tid < 64) {
                float c_ = acts[64 + tid]*cst + acts[tid]*acts[128 + tid];
                cst = c_;
                float h = acts[192 + tid]*tanhq(c_);
                hsm[tid] = h;
                h1B[t*64 + tid] = h;
            } else if (tid == 64 && (t & 3) == 0 && t) {
                relstore(&g_flag0[b], t);        // h1(0..t-1) visible
            } else if (tid >= 128 && tid < 132) {
                int l = tid - 128;
                ((float4*)(featsm + ((t + 2) & 1)*16))[l] = r4;   // feats(t+2) -> slot
                int nidx = t + 3;
                int idx = (nidx < T_) ? nidx : T_ - 1;
                if (nidx < T_ && (nidx & 255) == 0) {
                    int ck = nidx >> 8;
                    while (acqload(&g_done[b*8 + ck]) < 64) __nanosleep(256);
                }
                r4 = ((const float4*)(featsB + (size_t)idx*16))[l];
            }
            __syncthreads();
            // phase 3: whh0 dot with h1(t) + wih0 dot with feats(t+1)
            unsigned long long a0 = 0ull, a1 = 0ull;
            const ulonglong2* hp = (const ulonglong2*)hsm;
            #pragma unroll
            for (int q = 0; q < 16; ++q) {
                ulonglong2 hv = hp[q];
                fma2(a0, w0[2*q],   hv.x);
                fma2(a1, w0[2*q+1], hv.y);
            }
            const ulonglong2* fq = (const ulonglong2*)(featsm + ((t + 1) & 1)*16);
            #pragma unroll
            for (int q = 0; q < 4; ++q) {
                ulonglong2 fv = fq[q];
                fma2(a0, w0i[2*q],   fv.x);
                fma2(a1, w0i[2*q+1], fv.y);
            }
            float2 f0 = upk2(a0), f1 = upk2(a1);
            pg = bias0v + (f0.x + f0.y) + (f1.x + f1.y);   // gates0(t+1) pre-act
            acts[tid] = gact(tid, pg);
            __syncthreads();
        }
        if (tid == 0) relstore(&g_flag0[b], T_);
    } else if (blockIdx.x < 32) {
        // ============ mid: pre1 = wih1 @ h1 + bias (chunked GEMM, off critical path) ============
        const int b = blockIdx.x - 16;
        unsigned long long w1[32];
        {
            const float4* r1 = (const float4*)(wih1 + tid*64);
            #pragma unroll
            for (int q = 0; q < 16; ++q) {
                float4 a = r1[q]; w1[2*q] = pk2(a.x, a.y); w1[2*q+1] = pk2(a.z, a.w);
            }
        }
        const float bias1v = bih1[tid] + bhh1[tid];
        const float* h1B = g_h1 + (size_t)b * T_ * 64;
        float* pre1B = g_pre1 + (size_t)b * T_ * 256;
        int flagv = 0;

        for (int c = 0; c < T_/8; ++c) {
            int need = c*8 + 8;
            if (flagv < need) {
                do { flagv = acqload(&g_flag0[b]); if (flagv < need) __nanosleep(128); }
                while (flagv < need);
            }
            for (int i = tid; i < 512; i += 256) h1c[i] = h1B[c*512 + i];
            __syncthreads();
            #pragma unroll
            for (int j = 0; j < 8; ++j) {
                unsigned long long a0 = 0ull, a1 = 0ull;
                const ulonglong2* hp = (const ulonglong2*)(h1c + j*64);
                #pragma unroll
                for (int q = 0; q < 16; ++q) {
                    ulonglong2 hv = hp[q];
                    fma2(a0, w1[2*q],   hv.x);
                    fma2(a1, w1[2*q+1], hv.y);
                }
                float2 f0 = upk2(a0), f1 = upk2(a1);
                pre1B[(c*8 + j)*256 + tid] = bias1v + (f0.x + f0.y) + (f1.x + f1.y);
            }
            __syncthreads();
            if (tid == 0) relstore(&g_flag1[b], c*8 + 8);
        }
    } else {
        // ============ consumer: layer1 recurrence ============
        const int b = blockIdx.x - 32;
        unsigned long long w2r[32];
        {
            const float4* r2 = (const float4*)(whh1 + tid*64);
            #pragma unroll
            for (int q = 0; q < 16; ++q) {
                float4 a = r2[q]; w2r[2*q] = pk2(a.x, a.y); w2r[2*q+1] = pk2(a.z, a.w);
            }
        }
        const float* pre1B = g_pre1 + (size_t)b * T_ * 256;
        float* hB = g_h + (size_t)b * T_ * 64;
        float cst = 0.f;
        int flagv = 0;
        if (tid < 64) hsm[tid] = 0.f;
        while (flagv < 2) { flagv = acqload(&g_flag1[b]); if (flagv < 2) __nanosleep(1024); }
        float cg  = pre1B[tid];                  // gates1(0) pre-act (h2(-1)=0)
        float p1n = pre1B[256 + tid];            // pre1(1)
        acts[tid] = gact(tid, cg);
        __syncthreads();

        for (int t = 0; t < T_; ++t) {
            // phase 2: state update + h2 store
            if (tid < 64) {
                float c_ = acts[64 + tid]*cst + acts[tid]*acts[128 + tid];
                cst = c_;
                float h = acts[192 + tid]*tanhq(c_);
                hsm[tid] = h;
                hB[t*64 + tid] = h;
            }
            __syncthreads();
            // phase 3: whh1 dot with h2(t)
            unsigned long long a0 = 0ull, a1 = 0ull;
            const ulonglong2* hp = (const ulonglong2*)hsm;
            #pragma unroll
            for (int q = 0; q < 16; ++q) {
                ulonglong2 hv = hp[q];
                fma2(a0, w2r[2*q],   hv.x);
                fma2(a1, w2r[2*q+1], hv.y);
            }
            float2 f0 = upk2(a0), f1 = upk2(a1);
            cg = p1n + (f0.x + f0.y) + (f1.x + f1.y);   // gates1(t+1) pre-act
            acts[tid] = gact(tid, cg);
            int tn = (t + 2 < T_) ? t + 2 : T_ - 1;
            if (flagv < tn + 1) {
                do { flagv = acqload(&g_flag1[b]); if (flagv < tn + 1) __nanosleep(64); }
                while (flagv < tn + 1);
            }
            p1n = pre1B[tn*256 + tid];
            __syncthreads();
        }
    }
}

// ---------------- FC head ----------------
__global__ void __launch_bounds__(256) fc_kernel(
    const float* __restrict__ w1, const float* __restrict__ b1,
    const float* __restrict__ w2, const float* __restrict__ b2,
    float* __restrict__ out)
{
    __shared__ __align__(16) float w1s[2048];
    __shared__ float w2s[64];
    __shared__ float b1s[32];
    int tid = threadIdx.x;
    for (int i = tid; i < 2048; i += 256) w1s[i] = w1[i];
    if (tid < 64) w2s[tid] = w2[tid];
    if (tid < 32) b1s[tid] = b1[tid];
    __syncthreads();

    int gid = blockIdx.x*256 + tid;
    const float4* h4p = (const float4*)(g_h + (size_t)gid * 64);
    float4 h[16];
    #pragma unroll
    for (int q = 0; q < 16; ++q) h[q] = h4p[q];

    float l0 = b2[0], l1 = b2[1];
    #pragma unroll
    for (int i = 0; i < 32; ++i) {
        float acc = b1s[i];
        const float4* wr = (const float4*)(w1s + i*64);
        #pragma unroll
        for (int q = 0; q < 16; ++q) {
            float4 w4 = wr[q];
            acc += w4.x*h[q].x + w4.y*h[q].y + w4.z*h[q].z + w4.w*h[q].w;
        }
        acc = acc > 0.f ? acc : 0.f;
        l0 += w2s[i] * acc;
        l1 += w2s[32 + i] * acc;
    }
    ((float2*)out)[gid] = make_float2(l0, l1);
}

// ---------------- launch ----------------
extern "C" void kernel_launch(void* const* d_in, const int* in_sizes, int n_in,
                              void* d_out, int out_size)
{
    const float* x     = (const float*)d_in[0];
    const float* c1w   = (const float*)d_in[1];
    const float* c1b   = (const float*)d_in[2];
    const float* bn1g  = (const float*)d_in[3];
    const float* bn1b  = (const float*)d_in[4];
    const float* bn1m  = (const float*)d_in[5];
    const float* bn1v  = (const float*)d_in[6];
    const float* c2w   = (const float*)d_in[7];
    const float* c2b   = (const float*)d_in[8];
    const float* bn2g  = (const float*)d_in[9];
    const float* bn2b  = (const float*)d_in[10];
    const float* bn2m  = (const float*)d_in[11];
    const float* bn2v  = (const float*)d_in[12];
    const float* c3w   = (const float*)d_in[13];
    const float* c3b   = (const float*)d_in[14];
    const float* bn3g  = (const float*)d_in[15];
    const float* bn3b  = (const float*)d_in[16];
    const float* bn3m  = (const float*)d_in[17];
    const float* bn3v  = (const float*)d_in[18];
    const float* wih0  = (const float*)d_in[19];
    const float* whh0  = (const float*)d_in[20];
    const float* bih0  = (const float*)d_in[21];
    const float* bhh0  = (const float*)d_in[22];
    const float* wih1  = (const float*)d_in[23];
    const float* whh1  = (const float*)d_in[24];
    const float* bih1  = (const float*)d_in[25];
    const float* bhh1  = (const float*)d_in[26];
    const float* fc1w  = (const float*)d_in[27];
    const float* fc1b  = (const float*)d_in[28];
    const float* fc2w  = (const float*)d_in[29];
    const float* fc2b  = (const float*)d_in[30];

    cudaFuncSetAttribute(convA_kernel, cudaFuncAttributeMaxDynamicSharedMemorySize,
                         CA_SMEM_FLOATS * 4);
    cudaFuncSetAttribute(bnd_lstm_kernel, cudaFuncAttributeMaxDynamicSharedMemorySize,
                         BND_SMEM_FLOATS * 4);

    // Phase A: merged global conv stack (also resets pipeline state)
    convA_kernel<<<dim3(33, B_), 256, CA_SMEM_FLOATS * 4>>>(
        x, c1w, c1b, bn1g, bn1b, bn1m, bn1v,
        c2w, c2b, bn2g, bn2b, bn2m, bn2v,
        c3w, c3b, bn3g, bn3b, bn3m, bn3v);

    // Fused Phase B + LSTM: lstm CTAs claim SMs; bnd workers fill the rest via work queue.
    bnd_lstm_kernel<<<48 + NBND, 256, BND_SMEM_FLOATS * 4>>>(
        x, c1w, c1b, bn1g, bn1b, bn1m, bn1v,
        c2w, bn2g, bn2v, c3w, bn3g, bn3v,
        wih0, whh0, bih0, bhh0, wih1, whh1, bih1, bhh1);

    // FC head
    fc_kernel<<<(B_ * T_) / 256, 256>>>(fc1w, fc1b, fc2w, fc2b, (float*)d_out);
}